// round 12
// baseline (speedup 1.0000x reference)
#include <cuda_runtime.h>
#include <math.h>

#define BB   2
#define TT   2048
#define HID  1024
#define HH   16
#define HKV  4
#define MROWS  (BB*TT)          // 4096
#define NQKV   1536             // q(1024) | k(256) | v(256)
#define QCOLS  1024
#define NCHUNK 32               // T / 64
#define KT32   32               // K/32 for both GEMMs (K=1024)

// ---------------- scratch (device globals; no allocation) ------------------
__device__ float g_hstP[MROWS * HID];      // hs, tf32, fragment-major permuted
__device__ float g_qkv[MROWS * NQKV];      // [relu(q) | relu(k)->ke | v] row-major
__device__ float g_lg[MROWS * 256];        // log decay -> then be=exp(b)*0.125
__device__ float g_oattnP[MROWS * QCOLS];  // attention out, permuted for Wo GEMM
__device__ float g_WqkvP[HID * NQKV];      // [Wq|Wk|Wv] tf32 permuted (B layout)
__device__ float g_WoP[QCOLS * HID];       // Wo tf32 permuted (B layout)
__device__ float g_S[8 * NCHUNK * 64 * 64];// per-chunk entering states
__device__ float g_dl[8 * NCHUNK * 64];    // exp(b_last)

// ---------------- tf32 helpers ----------------------------------------------
__device__ __forceinline__ unsigned f2tf(float x) {
    unsigned r; asm("cvt.rna.tf32.f32 %0, %1;" : "=r"(r) : "f"(x)); return r;
}
__device__ __forceinline__ float f2tff(float x) {
    return __uint_as_float(f2tf(x));
}
__device__ __forceinline__ void mma_tf32(float* c, const unsigned* a,
                                         unsigned b0, unsigned b1) {
    asm volatile(
        "mma.sync.aligned.m16n8k8.row.col.f32.tf32.tf32.f32 "
        "{%0,%1,%2,%3},{%4,%5,%6,%7},{%8,%9},{%0,%1,%2,%3};"
        : "+f"(c[0]), "+f"(c[1]), "+f"(c[2]), "+f"(c[3])
        : "r"(a[0]), "r"(a[1]), "r"(a[2]), "r"(a[3]), "r"(b0), "r"(b1));
}
__device__ __forceinline__ void cp16(void* smem, const void* g) {
    unsigned s = (unsigned)__cvta_generic_to_shared(smem);
    asm volatile("cp.async.cg.shared.global [%0], [%1], 16;" :: "r"(s), "l"(g) : "memory");
}
__device__ __forceinline__ void cp_commit() {
    asm volatile("cp.async.commit_group;" ::: "memory");
}

// A-permuted index: element (r, c) of a row-major [M,1024] matrix.
__device__ __forceinline__ size_t aperm_idx(int r, int c) {
    int bm = r >> 7, rin = r & 127;
    int kt = c >> 5, cin = c & 31;
    int ks = cin >> 3, c8 = cin & 7;
    int gcn = c8 & 3, w = c8 >> 2;
    int rblk = rin >> 4, r16 = rin & 15;
    int grr = r16 & 7, rb = r16 >> 3;
    return ((size_t)(bm * KT32 + kt) << 12) +
           (size_t)(ks * 1024 + rblk * 128 + grr * 16 + gcn * 4 + w * 2 + rb);
}

// ---------------- BM=128 fragment-major GEMM (both GEMMs) ------------------
#define GSMEM_WORDS (3 * 2 * 4096)

__global__ void __launch_bounds__(256, 2) mma_gemm128(const float* __restrict__ Ap,
                                                      const float* __restrict__ Bp,
                                                      float* __restrict__ C,
                                                      int N, int relu_limit) {
    extern __shared__ unsigned sm[];
    unsigned (*As)[4096] = (unsigned(*)[4096])sm;
    unsigned (*Bs)[4096] = (unsigned(*)[4096])(sm + 3 * 4096);

    const int tid  = threadIdx.x;
    const int lane = tid & 31;
    const int warp = tid >> 5;
    const int row0 = blockIdx.y * 128;
    const int col0 = blockIdx.x * 128;
    const int wmt = (warp & 3) * 2;
    const int wn  = (warp >> 2) * 64;
    const int gr = lane >> 2, gc = lane & 3;

    float acc[2][8][4];
    #pragma unroll
    for (int i = 0; i < 2; i++)
        #pragma unroll
        for (int j = 0; j < 8; j++)
            #pragma unroll
            for (int l = 0; l < 4; l++) acc[i][j][l] = 0.f;

    const float* abase = Ap + ((size_t)blockIdx.y * KT32 << 12);
    const float* bbase = Bp + ((size_t)blockIdx.x * KT32 << 12);

    auto CPA = [&](int kt, int st) {
        const float* at = abase + ((size_t)kt << 12);
        const float* bt = bbase + ((size_t)kt << 12);
        #pragma unroll
        for (int i = 0; i < 4; i++) {
            int ch = tid + i * 256;
            cp16(&As[st][ch * 4], at + ch * 4);
        }
        #pragma unroll
        for (int i = 0; i < 4; i++) {
            int ch = tid + i * 256;
            cp16(&Bs[st][ch * 4], bt + ch * 4);
        }
        cp_commit();
    };

    auto COMP = [&](int st) {
        #pragma unroll
        for (int ks = 0; ks < 4; ks++) {
            unsigned a[2][4];
            #pragma unroll
            for (int mt = 0; mt < 2; mt++) {
                const uint4 av = *(const uint4*)&As[st][ks * 1024 + (wmt + mt) * 128 + gr * 16 + gc * 4];
                a[mt][0] = av.x; a[mt][1] = av.y; a[mt][2] = av.z; a[mt][3] = av.w;
            }
            #pragma unroll
            for (int nt = 0; nt < 8; nt++) {
                int nc = wn + nt * 8 + gr;
                const uint2 bv = *(const uint2*)&Bs[st][ks * 1024 + nc * 8 + gc * 2];
                mma_tf32(acc[0][nt], a[0], bv.x, bv.y);
                mma_tf32(acc[1][nt], a[1], bv.x, bv.y);
            }
        }
    };

    CPA(0, 0); CPA(1, 1);
    for (int kt = 0; kt < KT32; kt++) {
        if (kt + 1 < KT32) {
            asm volatile("cp.async.wait_group 1;" ::: "memory");
        } else {
            asm volatile("cp.async.wait_group 0;" ::: "memory");
        }
        __syncthreads();
        if (kt + 2 < KT32) CPA(kt + 2, (kt + 2) % 3);
        COMP(kt % 3);
    }

    #pragma unroll
    for (int mt = 0; mt < 2; mt++) {
        #pragma unroll
        for (int nt = 0; nt < 8; nt++) {
            int r  = row0 + (wmt + mt) * 16 + gr;
            int cc = col0 + wn + nt * 8 + gc * 2;
            float v0 = acc[mt][nt][0], v1 = acc[mt][nt][1];
            float v2 = acc[mt][nt][2], v3 = acc[mt][nt][3];
            if (cc < relu_limit) {
                v0 = fmaxf(v0, 0.f); v1 = fmaxf(v1, 0.f);
                v2 = fmaxf(v2, 0.f); v3 = fmaxf(v3, 0.f);
            }
            *(float2*)&C[(size_t)r * N + cc]       = make_float2(v0, v1);
            *(float2*)&C[(size_t)(r + 8) * N + cc] = make_float2(v2, v3);
        }
    }
}

// ---------------- prep: permute+round weights (B layout) -------------------
__global__ void prep_w(const float* __restrict__ Wq, const float* __restrict__ Wk,
                       const float* __restrict__ Wv, const float* __restrict__ Wo) {
    int i = blockIdx.x * 256 + threadIdx.x;     // 1,310,720 float2 total
    if (i < 786432) {                           // Wqkv: N=1536, 384 tiles
        int tile = i >> 11, inner2 = i & 2047;
        int ks = inner2 >> 9, nn = (inner2 >> 2) & 127, gcn = inner2 & 3;
        int bn = tile >> 5, kt = tile & 31;
        int k0 = kt * 32 + ks * 8 + gcn;
        int n  = bn * 128 + nn;
        float w0, w1;
        if (n < 1024)      { w0 = Wq[(size_t)k0 * 1024 + n];       w1 = Wq[(size_t)(k0 + 4) * 1024 + n]; }
        else if (n < 1280) { w0 = Wk[(size_t)k0 * 256 + n - 1024]; w1 = Wk[(size_t)(k0 + 4) * 256 + n - 1024]; }
        else               { w0 = Wv[(size_t)k0 * 256 + n - 1280]; w1 = Wv[(size_t)(k0 + 4) * 256 + n - 1280]; }
        g_WqkvP[(size_t)i * 2]     = f2tff(w0);
        g_WqkvP[(size_t)i * 2 + 1] = f2tff(w1);
    } else {                                    // Wo: N=1024, 256 tiles
        int j = i - 786432;
        int tile = j >> 11, inner2 = j & 2047;
        int ks = inner2 >> 9, nn = (inner2 >> 2) & 127, gcn = inner2 & 3;
        int bn = tile >> 5, kt = tile & 31;
        int k0 = kt * 32 + ks * 8 + gcn;
        int n  = bn * 128 + nn;
        g_WoP[(size_t)j * 2]     = f2tff(Wo[(size_t)k0 * 1024 + n]);
        g_WoP[(size_t)j * 2 + 1] = f2tff(Wo[(size_t)(k0 + 4) * 1024 + n]);
    }
}

// permute+round hs into A layout. One thread per output float4.
__global__ void conv_hs(const float* __restrict__ hs) {
    int o4 = blockIdx.x * 256 + threadIdx.x;    // 1M float4
    int tile = o4 >> 10, inner4 = o4 & 1023;
    int ks = inner4 >> 8, rblk = (inner4 >> 5) & 7, grr = (inner4 >> 2) & 7, gcn = inner4 & 3;
    int bm = tile >> 5, kt = tile & 31;
    int r0 = bm * 128 + rblk * 16 + grr;
    int c0 = kt * 32 + ks * 8 + gcn;
    float4 o;
    o.x = f2tff(hs[(size_t)r0 * HID + c0]);
    o.y = f2tff(hs[(size_t)(r0 + 8) * HID + c0]);
    o.z = f2tff(hs[(size_t)r0 * HID + c0 + 4]);
    o.w = f2tff(hs[(size_t)(r0 + 8) * HID + c0 + 4]);
    ((float4*)g_hstP)[o4] = o;
}

// ---------------- fused gate: lg = logsigmoid((hs@Wg1)@Wg2 + b)/16 ---------
__global__ void __launch_bounds__(256) gate_fused(const float* __restrict__ hs,
                                                  const float* __restrict__ Wg1,
                                                  const float* __restrict__ Wg2,
                                                  const float* __restrict__ bg2) {
    __shared__ float hs_s[32][128];
    __shared__ float w1_s[128][16];
    __shared__ float glow_s[32][16];
    __shared__ float w2_s[16][256];

    const int tid = threadIdx.x;
    const int row0 = blockIdx.x * 32;
    const int rowA = tid >> 4;
    const int col  = tid & 15;

    #pragma unroll
    for (int i = tid; i < 4096; i += 256)
        w2_s[i >> 8][i & 255] = Wg2[i];

    float acc0 = 0.f, acc1 = 0.f;
    for (int kt = 0; kt < 8; kt++) {
        __syncthreads();
        #pragma unroll
        for (int i = 0; i < 4; i++) {
            int ch = tid + i * 256;
            int r = ch >> 5, cc = (ch & 31) * 4;
            *(float4*)&hs_s[r][cc] = *(const float4*)&hs[(size_t)(row0 + r) * HID + kt * 128 + cc];
        }
        #pragma unroll
        for (int i = 0; i < 2; i++) {
            int ch = tid + i * 256;
            int kk = ch >> 2, cc = (ch & 3) * 4;
            *(float4*)&w1_s[kk][cc] = *(const float4*)&Wg1[(size_t)(kt * 128 + kk) * 16 + cc];
        }
        __syncthreads();
        #pragma unroll 8
        for (int k = 0; k < 128; k++) {
            float w = w1_s[k][col];
            acc0 = fmaf(hs_s[rowA][k], w, acc0);
            acc1 = fmaf(hs_s[rowA + 16][k], w, acc1);
        }
    }
    glow_s[rowA][col]      = acc0;
    glow_s[rowA + 16][col] = acc1;
    __syncthreads();

    const int c = tid;
    const float bias = bg2[c];
    #pragma unroll 4
    for (int r = 0; r < 32; r++) {
        float x = bias;
        #pragma unroll
        for (int j = 0; j < 16; j++) x = fmaf(glow_s[r][j], w2_s[j][c], x);
        float ls = fminf(x, 0.f) - log1pf(__expf(-fabsf(x)));
        g_lg[(size_t)(row0 + r) * 256 + c] = ls * 0.0625f;
    }
}

// ---------------- Phase A: cumsum; be=exp(b)/8 in place; scale k -----------
__global__ void __launch_bounds__(64) phaseA_kernel() {
    const int c   = blockIdx.x & 31;
    const int grp = blockIdx.x >> 5;
    const int b = grp >> 2, hk = grp & 3;
    const int d = threadIdx.x;
    float bacc = 0.f;
    const size_t row0 = (size_t)b * TT + c * 64;
    for (int t0 = 0; t0 < 64; t0 += 8) {
        float lg8[8], kv8[8];
        #pragma unroll
        for (int i = 0; i < 8; i++)
            lg8[i] = g_lg[(row0 + t0 + i) * 256 + hk * 64 + d];
        #pragma unroll
        for (int i = 0; i < 8; i++)
            kv8[i] = g_qkv[(row0 + t0 + i) * NQKV + 1024 + hk * 64 + d];
        #pragma unroll
        for (int i = 0; i < 8; i++) {
            bacc += lg8[i];
            g_lg[(row0 + t0 + i) * 256 + hk * 64 + d] = __expf(bacc) * 0.125f;
            g_qkv[(row0 + t0 + i) * NQKV + 1024 + hk * 64 + d] = kv8[i] * __expf(-bacc);
        }
    }
    g_dl[(grp * 32 + c) * 64 + d] = __expf(bacc);
}

// ---------------- Phase B: propagate states (cp.async double-buffered) -----
__global__ void __launch_bounds__(128) phaseB_kernel() {
    const int grp = blockIdx.x >> 3;
    const int vc  = blockIdx.x & 7;
    const int b = grp >> 2, hk = grp & 3;
    const int tid = threadIdx.x;
    const int v  = tid & 7;
    const int kg = tid >> 3;
    __shared__ __align__(16) float ke_s[2][64][64];
    __shared__ __align__(16) float v_s[2][64][8];
    float S0 = 0.f, S1 = 0.f, S2 = 0.f, S3 = 0.f;

    const size_t kbase = 1024 + hk * 64;
    const size_t vbase = 1280 + hk * 64 + vc * 8;

    auto ISSUE = [&](int c, int st) {
        const size_t row0 = (size_t)b * TT + c * 64;
        #pragma unroll
        for (int i = 0; i < 8; i++) {
            int idx = tid + i * 128;
            int t = idx >> 4, dq = idx & 15;
            cp16(&ke_s[st][t][dq * 4], &g_qkv[(row0 + t) * NQKV + kbase + dq * 4]);
        }
        {
            int t = tid >> 1, q4 = tid & 1;
            cp16(&v_s[st][t][q4 * 4], &g_qkv[(row0 + t) * NQKV + vbase + q4 * 4]);
        }
        cp_commit();
    };

    ISSUE(0, 0);

    for (int c = 0; c < NCHUNK; c++) {
        if (c + 1 < NCHUNK) {
            ISSUE(c + 1, (c + 1) & 1);
            asm volatile("cp.async.wait_group 1;" ::: "memory");
        } else {
            asm volatile("cp.async.wait_group 0;" ::: "memory");
        }
        __syncthreads();

        const int st = c & 1;
        const size_t sb_ = ((size_t)(grp * 32 + c) * 64 + kg * 4) * 64 + vc * 8 + v;
        g_S[sb_]       = S0;
        g_S[sb_ + 64]  = S1;
        g_S[sb_ + 128] = S2;
        g_S[sb_ + 192] = S3;

        #pragma unroll 4
        for (int t = 0; t < 64; t++) {
            const float4 kk = ((const float4*)ke_s[st][t])[kg];
            const float  vv = v_s[st][t][v];
            S0 = fmaf(kk.x, vv, S0);
            S1 = fmaf(kk.y, vv, S1);
            S2 = fmaf(kk.z, vv, S2);
            S3 = fmaf(kk.w, vv, S3);
        }
        const float4 dl4 = *(const float4*)&g_dl[(grp * 32 + c) * 64 + kg * 4];
        S0 *= dl4.x; S1 *= dl4.y; S2 *= dl4.z; S3 *= dl4.w;
        __syncthreads();
    }
}

// ---------------- Phase C: (grp, chunk) blocks; ke/v/S staged ONCE, 4 heads -
#define PC_LD 65
#define PC_SMEM_WORDS (5 * 64 * PC_LD)
__global__ void __launch_bounds__(256) phaseC_kernel(const float* __restrict__ gnw) {
    extern __shared__ unsigned smc[];
    unsigned* keT = smc;                    // [64][65]  ke^T (k=d major)
    unsigned* vs  = smc + 64 * PC_LD;       // [64][65]
    unsigned* Ss  = smc + 2 * 64 * PC_LD;   // [64][65]
    unsigned* qe  = smc + 3 * 64 * PC_LD;   // [64][65] per-head
    unsigned* Am  = smc + 4 * 64 * PC_LD;   // [64][65] masked A
    __shared__ float rs[64][2];

    const int c   = blockIdx.x & 31;
    const int grp = blockIdx.x >> 5;
    const int b = grp >> 2, hk = grp & 3;
    const int tid  = threadIdx.x;
    const int lane = tid & 31;
    const int warp = tid >> 5;
    const int wm = (warp & 3) * 16;
    const int wn = (warp >> 2) * 32;
    const int gr = lane >> 2, gc = lane & 3;
    const int rm = wm + gr;
    const size_t row0 = (size_t)b * TT + c * 64;

    // stage shared operands once
    for (int i = tid; i < 4096; i += 256) {
        int t = i >> 6, d = i & 63;
        keT[d * PC_LD + t] = f2tf(g_qkv[(row0 + t) * NQKV + 1024 + hk * 64 + d]);
        vs [t * PC_LD + d] = f2tf(g_qkv[(row0 + t) * NQKV + 1280 + hk * 64 + d]);
        Ss [t * PC_LD + d] = f2tf(g_S[((size_t)(grp * 32 + c) * 64 + t) * 64 + d]);
    }

    for (int h = 0; h < 4; h++) {
        // stage qe for this head (first iter: also covers keT/vs/Ss via same sync)
        for (int i = tid; i < 4096; i += 256) {
            int t = i >> 6, d = i & 63;
            float qv = g_qkv[(row0 + t) * NQKV + hk * 256 + h * 64 + d]
                     * g_lg[(row0 + t) * 256 + hk * 64 + d];
            qe[t * PC_LD + d] = f2tf(qv);
        }
        __syncthreads();

        // A = qe @ keT
        float accA[4][4];
        #pragma unroll
        for (int j = 0; j < 4; j++)
            #pragma unroll
            for (int l = 0; l < 4; l++) accA[j][l] = 0.f;
        #pragma unroll
        for (int ks = 0; ks < 8; ks++) {
            int cb = ks * 8 + gc;
            unsigned a[4];
            a[0] = qe[rm * PC_LD + cb];
            a[1] = qe[(rm + 8) * PC_LD + cb];
            a[2] = qe[rm * PC_LD + cb + 4];
            a[3] = qe[(rm + 8) * PC_LD + cb + 4];
            #pragma unroll
            for (int nt = 0; nt < 4; nt++) {
                int nc = wn + nt * 8 + gr;
                unsigned b0 = keT[cb * PC_LD + nc];
                unsigned b1 = keT[(cb + 4) * PC_LD + nc];
                mma_tf32(accA[nt], a, b0, b1);
            }
        }
        // causal mask -> Am
        #pragma unroll
        for (int nt = 0; nt < 4; nt++) {
            int s0 = wn + nt * 8 + gc * 2;
            Am[rm * PC_LD + s0]           = f2tf(s0     <= rm     ? accA[nt][0] : 0.f);
            Am[rm * PC_LD + s0 + 1]       = f2tf(s0 + 1 <= rm     ? accA[nt][1] : 0.f);
            Am[(rm + 8) * PC_LD + s0]     = f2tf(s0     <= rm + 8 ? accA[nt][2] : 0.f);
            Am[(rm + 8) * PC_LD + s0 + 1] = f2tf(s0 + 1 <= rm + 8 ? accA[nt][3] : 0.f);
        }
        __syncthreads();

        // O = Am @ v + qe @ S
        float acc[4][4];
        #pragma unroll
        for (int j = 0; j < 4; j++)
            #pragma unroll
            for (int l = 0; l < 4; l++) acc[j][l] = 0.f;
        #pragma unroll
        for (int ks = 0; ks < 8; ks++) {
            int cb = ks * 8 + gc;
            unsigned a[4];
            a[0] = Am[rm * PC_LD + cb];
            a[1] = Am[(rm + 8) * PC_LD + cb];
            a[2] = Am[rm * PC_LD + cb + 4];
            a[3] = Am[(rm + 8) * PC_LD + cb + 4];
            #pragma unroll
            for (int nt = 0; nt < 4; nt++) {
                int nc = wn + nt * 8 + gr;
                unsigned b0 = vs[cb * PC_LD + nc];
                unsigned b1 = vs[(cb + 4) * PC_LD + nc];
                mma_tf32(acc[nt], a, b0, b1);
            }
        }
        #pragma unroll
        for (int ks = 0; ks < 8; ks++) {
            int cb = ks * 8 + gc;
            unsigned a[4];
            a[0] = qe[rm * PC_LD + cb];
            a[1] = qe[(rm + 8) * PC_LD + cb];
            a[2] = qe[rm * PC_LD + cb + 4];
            a[3] = qe[(rm + 8) * PC_LD + cb + 4];
            #pragma unroll
            for (int nt = 0; nt < 4; nt++) {
                int nc = wn + nt * 8 + gr;
                unsigned b0 = Ss[cb * PC_LD + nc];
                unsigned b1 = Ss[(cb + 4) * PC_LD + nc];
                mma_tf32(acc[nt], a, b0, b1);
            }
        }

        // fused RMSNorm
        float ss0 = 0.f, ss1 = 0.f;
        #pragma unroll
        for (int nt = 0; nt < 4; nt++) {
            ss0 += acc[nt][0] * acc[nt][0] + acc[nt][1] * acc[nt][1];
            ss1 += acc[nt][2] * acc[nt][2] + acc[nt][3] * acc[nt][3];
        }
        ss0 += __shfl_xor_sync(0xffffffffu, ss0, 1);
        ss0 += __shfl_xor_sync(0xffffffffu, ss0, 2);
        ss1 += __shfl_xor_sync(0xffffffffu, ss1, 1);
        ss1 += __shfl_xor_sync(0xffffffffu, ss1, 2);
        if (gc == 0) {
            rs[rm][warp >> 2]     = ss0;
            rs[rm + 8][warp >> 2] = ss1;
        }
        __syncthreads();
        float r0 = rsqrtf((rs[rm][0] + rs[rm][1]) * (1.f / 64.f) + 1e-6f);
        float r1 = rsqrtf((rs[rm + 8][0] + rs[rm + 8][1]) * (1.f / 64.f) + 1e-6f);

        const int rowg = (int)row0 + rm;
        const int cbase = (hk * 4 + h) * 64;
        #pragma unroll
        for (int nt = 0; nt < 4; nt++) {
            #pragma unroll
            for (int j = 0; j < 2; j++) {
                int colg = cbase + wn + nt * 8 + gc * 2 + j;
                float gw = gnw[wn + nt * 8 + gc * 2 + j];
                g_oattnP[aperm_idx(rowg, colg)]     = f2tff(acc[nt][j]     * r0 * gw);
                g_oattnP[aperm_idx(rowg + 8, colg)] = f2tff(acc[nt][2 + j] * r1 * gw);
            }
        }
        __syncthreads();   // protect qe/Am/rs before next head
    }
}

// ---------------- launch -----------------------------------------------------
extern "C" void kernel_launch(void* const* d_in, const int* in_sizes, int n_in,
                              void* d_out, int out_size) {
    const float* hs  = (const float*)d_in[0];
    const float* Wq  = (const float*)d_in[1];
    const float* Wk  = (const float*)d_in[2];
    const float* Wv  = (const float*)d_in[3];
    const float* Wo  = (const float*)d_in[4];
    const float* Wg1 = (const float*)d_in[5];
    const float* Wg2 = (const float*)d_in[6];
    const float* bg2 = (const float*)d_in[7];
    const float* gnw = (const float*)d_in[8];
    float* out = (float*)d_out;

    float *phstP, *pqkv, *poattnP, *pwqkvP, *pwoP;
    cudaGetSymbolAddress((void**)&phstP,   g_hstP);
    cudaGetSymbolAddress((void**)&pqkv,    g_qkv);
    cudaGetSymbolAddress((void**)&poattnP, g_oattnP);
    cudaGetSymbolAddress((void**)&pwqkvP,  g_WqkvP);
    cudaGetSymbolAddress((void**)&pwoP,    g_WoP);

    cudaFuncSetAttribute(phaseC_kernel,
                         cudaFuncAttributeMaxDynamicSharedMemorySize,
                         PC_SMEM_WORDS * 4);
    cudaFuncSetAttribute(mma_gemm128,
                         cudaFuncAttributeMaxDynamicSharedMemorySize,
                         GSMEM_WORDS * 4);

    // prep: permute+round inputs/weights
    prep_w<<<5120, 256>>>(Wq, Wk, Wv, Wo);
    conv_hs<<<4096, 256>>>(hs);
    // fused gate (fp32 direct from hs)
    gate_fused<<<MROWS / 32, 256>>>(hs, Wg1, Wg2, bg2);

    // qkv = [relu(hs@Wq) | relu(hs@Wk) | hs@Wv] — BM=128 (proven best)
    mma_gemm128<<<dim3(NQKV / 128, MROWS / 128), 256, GSMEM_WORDS * 4>>>(
        phstP, pwqkvP, pqkv, NQKV, 1280);

    // chunked GLA
    phaseA_kernel<<<8 * NCHUNK, 64>>>();
    phaseB_kernel<<<64, 128>>>();
    phaseC_kernel<<<8 * NCHUNK, 256, PC_SMEM_WORDS * 4>>>(gnw);

    // out = oattn @ Wo
    mma_gemm128<<<dim3(HID / 128, MROWS / 128), 256, GSMEM_WORDS * 4>>>(
        poattnP, pwoP, out, HID, 0);
}

// round 14
// speedup vs baseline: 1.0796x; 1.0796x over previous
#include <cuda_runtime.h>
#include <math.h>

#define BB   2
#define TT   2048
#define HID  1024
#define HH   16
#define HKV  4
#define MROWS  (BB*TT)          // 4096
#define NQKV   1536             // q(1024) | k(256) | v(256)
#define QCOLS  1024
#define NCHUNK 32               // T / 64
#define KT32   32               // K/32 for both GEMMs (K=1024)

// ---------------- scratch (device globals; no allocation) ------------------
__device__ float g_hstP[MROWS * HID];      // hs, tf32, fragment-major permuted
__device__ float g_qkv[MROWS * NQKV];      // [relu(q) | relu(k)->ke | v] row-major
__device__ float g_lg[MROWS * 256];        // log decay -> then be=exp(b)*0.125
__device__ float g_oattnP[MROWS * QCOLS];  // attention out, permuted for Wo GEMM
__device__ float g_WqkvP[HID * NQKV];      // [Wq|Wk|Wv] tf32 permuted (B layout)
__device__ float g_WoP[QCOLS * HID];       // Wo tf32 permuted (B layout)
__device__ float g_S[8 * NCHUNK * 64 * 64];// per-chunk entering states
__device__ float g_dl[8 * NCHUNK * 64];    // exp(b_last)

// ---------------- tf32 helpers ----------------------------------------------
__device__ __forceinline__ unsigned f2tf(float x) {
    unsigned r; asm("cvt.rna.tf32.f32 %0, %1;" : "=r"(r) : "f"(x)); return r;
}
__device__ __forceinline__ float f2tff(float x) {
    return __uint_as_float(f2tf(x));
}
__device__ __forceinline__ void mma_tf32(float* c, const unsigned* a,
                                         unsigned b0, unsigned b1) {
    asm volatile(
        "mma.sync.aligned.m16n8k8.row.col.f32.tf32.tf32.f32 "
        "{%0,%1,%2,%3},{%4,%5,%6,%7},{%8,%9},{%0,%1,%2,%3};"
        : "+f"(c[0]), "+f"(c[1]), "+f"(c[2]), "+f"(c[3])
        : "r"(a[0]), "r"(a[1]), "r"(a[2]), "r"(a[3]), "r"(b0), "r"(b1));
}
__device__ __forceinline__ void cp16(void* smem, const void* g) {
    unsigned s = (unsigned)__cvta_generic_to_shared(smem);
    asm volatile("cp.async.cg.shared.global [%0], [%1], 16;" :: "r"(s), "l"(g) : "memory");
}
__device__ __forceinline__ void cp_commit() {
    asm volatile("cp.async.commit_group;" ::: "memory");
}

// A-permuted index: element (r, c) of a row-major [M,1024] matrix.
__device__ __forceinline__ size_t aperm_idx(int r, int c) {
    int bm = r >> 7, rin = r & 127;
    int kt = c >> 5, cin = c & 31;
    int ks = cin >> 3, c8 = cin & 7;
    int gcn = c8 & 3, w = c8 >> 2;
    int rblk = rin >> 4, r16 = rin & 15;
    int grr = r16 & 7, rb = r16 >> 3;
    return ((size_t)(bm * KT32 + kt) << 12) +
           (size_t)(ks * 1024 + rblk * 128 + grr * 16 + gcn * 4 + w * 2 + rb);
}

// ---------------- BM=128 fragment-major GEMM (both GEMMs) ------------------
#define GSMEM_WORDS (3 * 2 * 4096)

__global__ void __launch_bounds__(256, 2) mma_gemm128(const float* __restrict__ Ap,
                                                      const float* __restrict__ Bp,
                                                      float* __restrict__ C,
                                                      int N, int relu_limit) {
    extern __shared__ unsigned sm[];
    unsigned (*As)[4096] = (unsigned(*)[4096])sm;
    unsigned (*Bs)[4096] = (unsigned(*)[4096])(sm + 3 * 4096);

    const int tid  = threadIdx.x;
    const int lane = tid & 31;
    const int warp = tid >> 5;
    const int row0 = blockIdx.y * 128;
    const int col0 = blockIdx.x * 128;
    const int wmt = (warp & 3) * 2;
    const int wn  = (warp >> 2) * 64;
    const int gr = lane >> 2, gc = lane & 3;

    float acc[2][8][4];
    #pragma unroll
    for (int i = 0; i < 2; i++)
        #pragma unroll
        for (int j = 0; j < 8; j++)
            #pragma unroll
            for (int l = 0; l < 4; l++) acc[i][j][l] = 0.f;

    const float* abase = Ap + ((size_t)blockIdx.y * KT32 << 12);
    const float* bbase = Bp + ((size_t)blockIdx.x * KT32 << 12);

    auto CPA = [&](int kt, int st) {
        const float* at = abase + ((size_t)kt << 12);
        const float* bt = bbase + ((size_t)kt << 12);
        #pragma unroll
        for (int i = 0; i < 4; i++) {
            int ch = tid + i * 256;
            cp16(&As[st][ch * 4], at + ch * 4);
        }
        #pragma unroll
        for (int i = 0; i < 4; i++) {
            int ch = tid + i * 256;
            cp16(&Bs[st][ch * 4], bt + ch * 4);
        }
        cp_commit();
    };

    auto COMP = [&](int st) {
        #pragma unroll
        for (int ks = 0; ks < 4; ks++) {
            unsigned a[2][4];
            #pragma unroll
            for (int mt = 0; mt < 2; mt++) {
                const uint4 av = *(const uint4*)&As[st][ks * 1024 + (wmt + mt) * 128 + gr * 16 + gc * 4];
                a[mt][0] = av.x; a[mt][1] = av.y; a[mt][2] = av.z; a[mt][3] = av.w;
            }
            #pragma unroll
            for (int nt = 0; nt < 8; nt++) {
                int nc = wn + nt * 8 + gr;
                const uint2 bv = *(const uint2*)&Bs[st][ks * 1024 + nc * 8 + gc * 2];
                mma_tf32(acc[0][nt], a[0], bv.x, bv.y);
                mma_tf32(acc[1][nt], a[1], bv.x, bv.y);
            }
        }
    };

    CPA(0, 0); CPA(1, 1);
    for (int kt = 0; kt < KT32; kt++) {
        if (kt + 1 < KT32) {
            asm volatile("cp.async.wait_group 1;" ::: "memory");
        } else {
            asm volatile("cp.async.wait_group 0;" ::: "memory");
        }
        __syncthreads();
        if (kt + 2 < KT32) CPA(kt + 2, (kt + 2) % 3);
        COMP(kt % 3);
    }

    #pragma unroll
    for (int mt = 0; mt < 2; mt++) {
        #pragma unroll
        for (int nt = 0; nt < 8; nt++) {
            int r  = row0 + (wmt + mt) * 16 + gr;
            int cc = col0 + wn + nt * 8 + gc * 2;
            float v0 = acc[mt][nt][0], v1 = acc[mt][nt][1];
            float v2 = acc[mt][nt][2], v3 = acc[mt][nt][3];
            if (cc < relu_limit) {
                v0 = fmaxf(v0, 0.f); v1 = fmaxf(v1, 0.f);
                v2 = fmaxf(v2, 0.f); v3 = fmaxf(v3, 0.f);
            }
            *(float2*)&C[(size_t)r * N + cc]       = make_float2(v0, v1);
            *(float2*)&C[(size_t)(r + 8) * N + cc] = make_float2(v2, v3);
        }
    }
}

// ---------------- prep: Wqkv fragment-major (B layout) ----------------------
__global__ void prep_wqkv(const float* __restrict__ Wq, const float* __restrict__ Wk,
                          const float* __restrict__ Wv) {
    int i = blockIdx.x * 256 + threadIdx.x;     // 786432 float2
    int tile = i >> 11, inner2 = i & 2047;
    int ks = inner2 >> 9, nn = (inner2 >> 2) & 127, gcn = inner2 & 3;
    int bn = tile >> 5, kt = tile & 31;
    int k0 = kt * 32 + ks * 8 + gcn;
    int n  = bn * 128 + nn;
    float w0, w1;
    if (n < 1024)      { w0 = Wq[(size_t)k0 * 1024 + n];       w1 = Wq[(size_t)(k0 + 4) * 1024 + n]; }
    else if (n < 1280) { w0 = Wk[(size_t)k0 * 256 + n - 1024]; w1 = Wk[(size_t)(k0 + 4) * 256 + n - 1024]; }
    else               { w0 = Wv[(size_t)k0 * 256 + n - 1280]; w1 = Wv[(size_t)(k0 + 4) * 256 + n - 1280]; }
    g_WqkvP[(size_t)i * 2]     = f2tff(w0);
    g_WqkvP[(size_t)i * 2 + 1] = f2tff(w1);
}

// ---------------- prep: Wo fragment-major (B layout) ------------------------
__global__ void prep_wo(const float* __restrict__ Wo) {
    int j = blockIdx.x * 256 + threadIdx.x;     // 524288 float2
    int tile = j >> 11, inner2 = j & 2047;
    int ks = inner2 >> 9, nn = (inner2 >> 2) & 127, gcn = inner2 & 3;
    int bn = tile >> 5, kt = tile & 31;
    int k0 = kt * 32 + ks * 8 + gcn;
    int n  = bn * 128 + nn;
    g_WoP[(size_t)j * 2]     = f2tff(Wo[(size_t)k0 * 1024 + n]);
    g_WoP[(size_t)j * 2 + 1] = f2tff(Wo[(size_t)(k0 + 4) * 1024 + n]);
}

// permute+round hs into A layout. One thread per output float4.
__global__ void conv_hs(const float* __restrict__ hs) {
    int o4 = blockIdx.x * 256 + threadIdx.x;    // 1M float4
    int tile = o4 >> 10, inner4 = o4 & 1023;
    int ks = inner4 >> 8, rblk = (inner4 >> 5) & 7, grr = (inner4 >> 2) & 7, gcn = inner4 & 3;
    int bm = tile >> 5, kt = tile & 31;
    int r0 = bm * 128 + rblk * 16 + grr;
    int c0 = kt * 32 + ks * 8 + gcn;
    float4 o;
    o.x = f2tff(hs[(size_t)r0 * HID + c0]);
    o.y = f2tff(hs[(size_t)(r0 + 8) * HID + c0]);
    o.z = f2tff(hs[(size_t)r0 * HID + c0 + 4]);
    o.w = f2tff(hs[(size_t)(r0 + 8) * HID + c0 + 4]);
    ((float4*)g_hstP)[o4] = o;
}

// ---------------- fused gate: lg = logsigmoid((hs@Wg1)@Wg2 + b)/16 ---------
__global__ void __launch_bounds__(256) gate_fused(const float* __restrict__ hs,
                                                  const float* __restrict__ Wg1,
                                                  const float* __restrict__ Wg2,
                                                  const float* __restrict__ bg2) {
    __shared__ float hs_s[32][128];
    __shared__ float w1_s[128][16];
    __shared__ float glow_s[32][16];
    __shared__ float w2_s[16][256];

    const int tid = threadIdx.x;
    const int row0 = blockIdx.x * 32;
    const int rowA = tid >> 4;
    const int col  = tid & 15;

    #pragma unroll
    for (int i = tid; i < 4096; i += 256)
        w2_s[i >> 8][i & 255] = Wg2[i];

    float acc0 = 0.f, acc1 = 0.f;
    for (int kt = 0; kt < 8; kt++) {
        __syncthreads();
        #pragma unroll
        for (int i = 0; i < 4; i++) {
            int ch = tid + i * 256;
            int r = ch >> 5, cc = (ch & 31) * 4;
            *(float4*)&hs_s[r][cc] = *(const float4*)&hs[(size_t)(row0 + r) * HID + kt * 128 + cc];
        }
        #pragma unroll
        for (int i = 0; i < 2; i++) {
            int ch = tid + i * 256;
            int kk = ch >> 2, cc = (ch & 3) * 4;
            *(float4*)&w1_s[kk][cc] = *(const float4*)&Wg1[(size_t)(kt * 128 + kk) * 16 + cc];
        }
        __syncthreads();
        #pragma unroll 8
        for (int k = 0; k < 128; k++) {
            float w = w1_s[k][col];
            acc0 = fmaf(hs_s[rowA][k], w, acc0);
            acc1 = fmaf(hs_s[rowA + 16][k], w, acc1);
        }
    }
    glow_s[rowA][col]      = acc0;
    glow_s[rowA + 16][col] = acc1;
    __syncthreads();

    const int c = tid;
    const float bias = bg2[c];
    #pragma unroll 4
    for (int r = 0; r < 32; r++) {
        float x = bias;
        #pragma unroll
        for (int j = 0; j < 16; j++) x = fmaf(glow_s[r][j], w2_s[j][c], x);
        float ls = fminf(x, 0.f) - log1pf(__expf(-fabsf(x)));
        g_lg[(size_t)(row0 + r) * 256 + c] = ls * 0.0625f;
    }
}

// ---------------- Phase A: cumsum; be=exp(b)/8 in place; scale k -----------
__global__ void __launch_bounds__(64) phaseA_kernel() {
    const int c   = blockIdx.x & 31;
    const int grp = blockIdx.x >> 5;
    const int b = grp >> 2, hk = grp & 3;
    const int d = threadIdx.x;
    float bacc = 0.f;
    const size_t row0 = (size_t)b * TT + c * 64;
    for (int t0 = 0; t0 < 64; t0 += 8) {
        float lg8[8], kv8[8];
        #pragma unroll
        for (int i = 0; i < 8; i++)
            lg8[i] = g_lg[(row0 + t0 + i) * 256 + hk * 64 + d];
        #pragma unroll
        for (int i = 0; i < 8; i++)
            kv8[i] = g_qkv[(row0 + t0 + i) * NQKV + 1024 + hk * 64 + d];
        #pragma unroll
        for (int i = 0; i < 8; i++) {
            bacc += lg8[i];
            g_lg[(row0 + t0 + i) * 256 + hk * 64 + d] = __expf(bacc) * 0.125f;
            g_qkv[(row0 + t0 + i) * NQKV + 1024 + hk * 64 + d] = kv8[i] * __expf(-bacc);
        }
    }
    g_dl[(grp * 32 + c) * 64 + d] = __expf(bacc);
}

// ---------------- Phase B: propagate states (cp.async double-buffered) -----
// Per-chunk partial sums with 2 accumulator sets to halve the FMA chain.
__global__ void __launch_bounds__(128) phaseB_kernel() {
    const int grp = blockIdx.x >> 3;
    const int vc  = blockIdx.x & 7;
    const int b = grp >> 2, hk = grp & 3;
    const int tid = threadIdx.x;
    const int v  = tid & 7;
    const int kg = tid >> 3;
    __shared__ __align__(16) float ke_s[2][64][64];
    __shared__ __align__(16) float v_s[2][64][8];
    float S0 = 0.f, S1 = 0.f, S2 = 0.f, S3 = 0.f;

    const size_t kbase = 1024 + hk * 64;
    const size_t vbase = 1280 + hk * 64 + vc * 8;

    auto ISSUE = [&](int c, int st) {
        const size_t row0 = (size_t)b * TT + c * 64;
        #pragma unroll
        for (int i = 0; i < 8; i++) {
            int idx = tid + i * 128;
            int t = idx >> 4, dq = idx & 15;
            cp16(&ke_s[st][t][dq * 4], &g_qkv[(row0 + t) * NQKV + kbase + dq * 4]);
        }
        {
            int t = tid >> 1, q4 = tid & 1;
            cp16(&v_s[st][t][q4 * 4], &g_qkv[(row0 + t) * NQKV + vbase + q4 * 4]);
        }
        cp_commit();
    };

    ISSUE(0, 0);

    for (int c = 0; c < NCHUNK; c++) {
        if (c + 1 < NCHUNK) {
            ISSUE(c + 1, (c + 1) & 1);
            asm volatile("cp.async.wait_group 1;" ::: "memory");
        } else {
            asm volatile("cp.async.wait_group 0;" ::: "memory");
        }
        __syncthreads();

        const int st = c & 1;
        const size_t sb_ = ((size_t)(grp * 32 + c) * 64 + kg * 4) * 64 + vc * 8 + v;
        g_S[sb_]       = S0;
        g_S[sb_ + 64]  = S1;
        g_S[sb_ + 128] = S2;
        g_S[sb_ + 192] = S3;

        float Pa0 = 0.f, Pa1 = 0.f, Pa2 = 0.f, Pa3 = 0.f;
        float Pb0 = 0.f, Pb1 = 0.f, Pb2 = 0.f, Pb3 = 0.f;
        #pragma unroll 4
        for (int t = 0; t < 64; t += 2) {
            const float4 ka = ((const float4*)ke_s[st][t])[kg];
            const float  va = v_s[st][t][v];
            Pa0 = fmaf(ka.x, va, Pa0);
            Pa1 = fmaf(ka.y, va, Pa1);
            Pa2 = fmaf(ka.z, va, Pa2);
            Pa3 = fmaf(ka.w, va, Pa3);
            const float4 kb = ((const float4*)ke_s[st][t + 1])[kg];
            const float  vb = v_s[st][t + 1][v];
            Pb0 = fmaf(kb.x, vb, Pb0);
            Pb1 = fmaf(kb.y, vb, Pb1);
            Pb2 = fmaf(kb.z, vb, Pb2);
            Pb3 = fmaf(kb.w, vb, Pb3);
        }
        const float4 dl4 = *(const float4*)&g_dl[(grp * 32 + c) * 64 + kg * 4];
        S0 = dl4.x * (S0 + Pa0 + Pb0);
        S1 = dl4.y * (S1 + Pa1 + Pb1);
        S2 = dl4.z * (S2 + Pa2 + Pb2);
        S3 = dl4.w * (S3 + Pa3 + Pb3);
        __syncthreads();
    }
}

// ---------------- Phase C (R10): per (grp,head,chunk) blocks ----------------
#define PC_LD 65
__global__ void __launch_bounds__(256) phaseC_kernel(const float* __restrict__ gnw) {
    extern __shared__ unsigned smc[];
    unsigned* qe  = smc;
    unsigned* keT = smc + 64 * PC_LD;
    unsigned* vs  = smc + 2 * 64 * PC_LD;
    unsigned* Ss  = smc + 3 * 64 * PC_LD;
    __shared__ float rs[64][2];

    const int c   = blockIdx.x & 31;
    const int h   = (blockIdx.x >> 5) & 3;
    const int grp = blockIdx.x >> 7;
    const int b = grp >> 2, hk = grp & 3;
    const int tid  = threadIdx.x;
    const int lane = tid & 31;
    const int warp = tid >> 5;
    const int wm = (warp & 3) * 16;
    const int wn = (warp >> 2) * 32;
    const int gr = lane >> 2, gc = lane & 3;
    const size_t row0 = (size_t)b * TT + c * 64;

    for (int i = tid; i < 4096; i += 256) {
        int t = i >> 6, d = i & 63;
        float qv = g_qkv[(row0 + t) * NQKV + hk * 256 + h * 64 + d]
                 * g_lg[(row0 + t) * 256 + hk * 64 + d];
        qe [t * PC_LD + d] = f2tf(qv);
        keT[d * PC_LD + t] = f2tf(g_qkv[(row0 + t) * NQKV + 1024 + hk * 64 + d]);
        vs [t * PC_LD + d] = f2tf(g_qkv[(row0 + t) * NQKV + 1280 + hk * 64 + d]);
        Ss [t * PC_LD + d] = f2tf(g_S[((size_t)(grp * 32 + c) * 64 + t) * 64 + d]);
    }
    __syncthreads();

    float accA[4][4];
    #pragma unroll
    for (int j = 0; j < 4; j++)
        #pragma unroll
        for (int l = 0; l < 4; l++) accA[j][l] = 0.f;
    const int rm = wm + gr;
    #pragma unroll
    for (int ks = 0; ks < 8; ks++) {
        int cb = ks * 8 + gc;
        unsigned a[4];
        a[0] = qe[rm * PC_LD + cb];
        a[1] = qe[(rm + 8) * PC_LD + cb];
        a[2] = qe[rm * PC_LD + cb + 4];
        a[3] = qe[(rm + 8) * PC_LD + cb + 4];
        #pragma unroll
        for (int nt = 0; nt < 4; nt++) {
            int nc = wn + nt * 8 + gr;
            unsigned b0 = keT[cb * PC_LD + nc];
            unsigned b1 = keT[(cb + 4) * PC_LD + nc];
            mma_tf32(accA[nt], a, b0, b1);
        }
    }
    __syncthreads();
    #pragma unroll
    for (int nt = 0; nt < 4; nt++) {
        int s0 = wn + nt * 8 + gc * 2;
        keT[rm * PC_LD + s0]           = f2tf(s0     <= rm     ? accA[nt][0] : 0.f);
        keT[rm * PC_LD + s0 + 1]       = f2tf(s0 + 1 <= rm     ? accA[nt][1] : 0.f);
        keT[(rm + 8) * PC_LD + s0]     = f2tf(s0     <= rm + 8 ? accA[nt][2] : 0.f);
        keT[(rm + 8) * PC_LD + s0 + 1] = f2tf(s0 + 1 <= rm + 8 ? accA[nt][3] : 0.f);
    }
    __syncthreads();

    float acc[4][4];
    #pragma unroll
    for (int j = 0; j < 4; j++)
        #pragma unroll
        for (int l = 0; l < 4; l++) acc[j][l] = 0.f;
    #pragma unroll
    for (int ks = 0; ks < 8; ks++) {
        int cb = ks * 8 + gc;
        unsigned a[4];
        a[0] = keT[rm * PC_LD + cb];
        a[1] = keT[(rm + 8) * PC_LD + cb];
        a[2] = keT[rm * PC_LD + cb + 4];
        a[3] = keT[(rm + 8) * PC_LD + cb + 4];
        #pragma unroll
        for (int nt = 0; nt < 4; nt++) {
            int nc = wn + nt * 8 + gr;
            unsigned b0 = vs[cb * PC_LD + nc];
            unsigned b1 = vs[(cb + 4) * PC_LD + nc];
            mma_tf32(acc[nt], a, b0, b1);
        }
    }
    #pragma unroll
    for (int ks = 0; ks < 8; ks++) {
        int cb = ks * 8 + gc;
        unsigned a[4];
        a[0] = qe[rm * PC_LD + cb];
        a[1] = qe[(rm + 8) * PC_LD + cb];
        a[2] = qe[rm * PC_LD + cb + 4];
        a[3] = qe[(rm + 8) * PC_LD + cb + 4];
        #pragma unroll
        for (int nt = 0; nt < 4; nt++) {
            int nc = wn + nt * 8 + gr;
            unsigned b0 = Ss[cb * PC_LD + nc];
            unsigned b1 = Ss[(cb + 4) * PC_LD + nc];
            mma_tf32(acc[nt], a, b0, b1);
        }
    }

    float ss0 = 0.f, ss1 = 0.f;
    #pragma unroll
    for (int nt = 0; nt < 4; nt++) {
        ss0 += acc[nt][0] * acc[nt][0] + acc[nt][1] * acc[nt][1];
        ss1 += acc[nt][2] * acc[nt][2] + acc[nt][3] * acc[nt][3];
    }
    ss0 += __shfl_xor_sync(0xffffffffu, ss0, 1);
    ss0 += __shfl_xor_sync(0xffffffffu, ss0, 2);
    ss1 += __shfl_xor_sync(0xffffffffu, ss1, 1);
    ss1 += __shfl_xor_sync(0xffffffffu, ss1, 2);
    if (gc == 0) {
        rs[rm][warp >> 2]     = ss0;
        rs[rm + 8][warp >> 2] = ss1;
    }
    __syncthreads();
    float r0 = rsqrtf((rs[rm][0] + rs[rm][1]) * (1.f / 64.f) + 1e-6f);
    float r1 = rsqrtf((rs[rm + 8][0] + rs[rm + 8][1]) * (1.f / 64.f) + 1e-6f);

    const int rowg = (int)row0 + rm;
    const int cbase = (hk * 4 + h) * 64;
    #pragma unroll
    for (int nt = 0; nt < 4; nt++) {
        #pragma unroll
        for (int j = 0; j < 2; j++) {
            int colg = cbase + wn + nt * 8 + gc * 2 + j;
            float gw = gnw[wn + nt * 8 + gc * 2 + j];
            g_oattnP[aperm_idx(rowg, colg)]     = f2tff(acc[nt][j]     * r0 * gw);
            g_oattnP[aperm_idx(rowg + 8, colg)] = f2tff(acc[nt][2 + j] * r1 * gw);
        }
    }
}

// ---------------- launch -----------------------------------------------------
extern "C" void kernel_launch(void* const* d_in, const int* in_sizes, int n_in,
                              void* d_out, int out_size) {
    const float* hs  = (const float*)d_in[0];
    const float* Wq  = (const float*)d_in[1];
    const float* Wk  = (const float*)d_in[2];
    const float* Wv  = (const float*)d_in[3];
    const float* Wo  = (const float*)d_in[4];
    const float* Wg1 = (const float*)d_in[5];
    const float* Wg2 = (const float*)d_in[6];
    const float* bg2 = (const float*)d_in[7];
    const float* gnw = (const float*)d_in[8];
    float* out = (float*)d_out;

    float *phstP, *pqkv, *poattnP, *pwqkvP, *pwoP;
    cudaGetSymbolAddress((void**)&phstP,   g_hstP);
    cudaGetSymbolAddress((void**)&pqkv,    g_qkv);
    cudaGetSymbolAddress((void**)&poattnP, g_oattnP);
    cudaGetSymbolAddress((void**)&pwqkvP,  g_WqkvP);
    cudaGetSymbolAddress((void**)&pwoP,    g_WoP);

    cudaFuncSetAttribute(phaseC_kernel,
                         cudaFuncAttributeMaxDynamicSharedMemorySize,
                         4 * 64 * PC_LD * 4);
    cudaFuncSetAttribute(mma_gemm128,
                         cudaFuncAttributeMaxDynamicSharedMemorySize,
                         GSMEM_WORDS * 4);

    // side stream + fork/join events (created once, outside graph capture —
    // first call is the uncaptured correctness run)
    static cudaStream_t s1 = nullptr;
    static cudaEvent_t evFork = nullptr, evJoin = nullptr;
    if (!s1) {
        cudaStreamCreateWithFlags(&s1, cudaStreamNonBlocking);
        cudaEventCreateWithFlags(&evFork, cudaEventDisableTiming);
        cudaEventCreateWithFlags(&evJoin, cudaEventDisableTiming);
    }

    // fork: side stream runs gate + Wo prep concurrently with main chain
    cudaEventRecord(evFork, 0);
    cudaStreamWaitEvent(s1, evFork, 0);
    gate_fused<<<MROWS / 32, 256, 0, s1>>>(hs, Wg1, Wg2, bg2);
    prep_wo<<<2048, 256, 0, s1>>>(Wo);
    cudaEventRecord(evJoin, s1);

    // main chain: prep qkv weights + hs, then qkv GEMM
    prep_wqkv<<<3072, 256>>>(Wq, Wk, Wv);
    conv_hs<<<4096, 256>>>(hs);
    mma_gemm128<<<dim3(NQKV / 128, MROWS / 128), 256, GSMEM_WORDS * 4>>>(
        phstP, pwqkvP, pqkv, NQKV, 1280);

    // join: phaseA needs gate's g_lg; Wo GEMM (later) needs g_WoP
    cudaStreamWaitEvent(0, evJoin, 0);

    // chunked GLA
    phaseA_kernel<<<8 * NCHUNK, 64>>>();
    phaseB_kernel<<<64, 128>>>();
    phaseC_kernel<<<8 * 4 * NCHUNK, 256, 4 * 64 * PC_LD * 4>>>(gnw);

    // out = oattn @ Wo
    mma_gemm128<<<dim3(HID / 128, MROWS / 128), 256, GSMEM_WORDS * 4>>>(
        poattnP, pwoP, out, HID, 0);
}

// round 15
// speedup vs baseline: 1.3461x; 1.2468x over previous
#include <cuda_runtime.h>
#include <cuda_fp16.h>
#include <math.h>

#define BB   2
#define TT   2048
#define HID  1024
#define HH   16
#define HKV  4
#define MROWS  (BB*TT)          // 4096
#define NQKV   1536             // q(1024) | k(256) | v(256)
#define QCOLS  1024
#define NCHUNK 32               // T / 64
#define KT32   32               // K/32 tiles (K=1024)

// ---------------- scratch (device globals; no allocation) ------------------
__device__ unsigned g_hstH[MROWS * HID / 2];     // hs fp16, fragment-major (A)
__device__ float    g_qkv[MROWS * NQKV];         // [relu(q)|relu(k)->ke|v] fp32 row-major
__device__ float    g_lg[MROWS * 256];           // log decay -> be=exp(b)*0.125
__device__ unsigned g_oattnH[MROWS * QCOLS / 2]; // attention out fp16, fragment-major (A)
__device__ unsigned g_WqkvH[HID * NQKV / 2];     // [Wq|Wk|Wv] fp16 fragment-major (B)
__device__ unsigned g_WoH[QCOLS * HID / 2];      // Wo fp16 fragment-major (B)
__device__ float    g_S[8 * NCHUNK * 64 * 64];   // per-chunk entering states
__device__ float    g_dl[8 * NCHUNK * 64];       // exp(b_last)

// ---------------- helpers ----------------------------------------------------
__device__ __forceinline__ unsigned f2tf(float x) {
    unsigned r; asm("cvt.rna.tf32.f32 %0, %1;" : "=r"(r) : "f"(x)); return r;
}
__device__ __forceinline__ void mma_tf32(float* c, const unsigned* a,
                                         unsigned b0, unsigned b1) {
    asm volatile(
        "mma.sync.aligned.m16n8k8.row.col.f32.tf32.tf32.f32 "
        "{%0,%1,%2,%3},{%4,%5,%6,%7},{%8,%9},{%0,%1,%2,%3};"
        : "+f"(c[0]), "+f"(c[1]), "+f"(c[2]), "+f"(c[3])
        : "r"(a[0]), "r"(a[1]), "r"(a[2]), "r"(a[3]), "r"(b0), "r"(b1));
}
__device__ __forceinline__ void mma_f16(float* c, const unsigned* a,
                                        unsigned b0, unsigned b1) {
    asm volatile(
        "mma.sync.aligned.m16n8k16.row.col.f32.f16.f16.f32 "
        "{%0,%1,%2,%3},{%4,%5,%6,%7},{%8,%9},{%0,%1,%2,%3};"
        : "+f"(c[0]), "+f"(c[1]), "+f"(c[2]), "+f"(c[3])
        : "r"(a[0]), "r"(a[1]), "r"(a[2]), "r"(a[3]), "r"(b0), "r"(b1));
}
__device__ __forceinline__ unsigned pack2h(float lo, float hi) {
    __half2 h = __floats2half2_rn(lo, hi);
    return *(unsigned*)&h;
}
__device__ __forceinline__ void cp16(void* smem, const void* g) {
    unsigned s = (unsigned)__cvta_generic_to_shared(smem);
    asm volatile("cp.async.cg.shared.global [%0], [%1], 16;" :: "r"(s), "l"(g) : "memory");
}
__device__ __forceinline__ void cp_commit() {
    asm volatile("cp.async.commit_group;" ::: "memory");
}

// word (half-pair) index of (r, c[even]) in the fp16 fragment-major A layout
__device__ __forceinline__ size_t aperm16w(int r, int c) {
    int bm = r >> 7, rin = r & 127;
    int kt = c >> 5, cin = c & 31;
    int ks = cin >> 4, cw = cin & 15;
    int w8 = cw >> 3, c8 = cw & 7;
    int gcn = c8 >> 1;
    int rblk = rin >> 4, r16 = rin & 15;
    int grr = r16 & 7, rb = r16 >> 3;
    return ((size_t)(bm * KT32 + kt)) * 2048 +
           (size_t)(ks * 1024 + rblk * 128 + grr * 16 + gcn * 4 + w8 * 2 + rb);
}

// ---------------- fp16 fragment-major GEMM: C = act(A @ B) ------------------
// BM=128, BN=128, BK=32 (2 k16-steps), 3-stage cp.async ring, 8 warps (4m x 2n).
#define H_STAGE 4096
#define HSMEM_WORDS (3 * H_STAGE)

__global__ void __launch_bounds__(256, 2) mma_gemm16(const unsigned* __restrict__ Ap,
                                                     const unsigned* __restrict__ Bp,
                                                     float* __restrict__ C,
                                                     int N, int relu_limit) {
    extern __shared__ unsigned sm[];

    const int tid  = threadIdx.x;
    const int lane = tid & 31;
    const int warp = tid >> 5;
    const int row0 = blockIdx.y * 128;
    const int col0 = blockIdx.x * 128;
    const int wmt = (warp & 3) * 2;
    const int wn  = (warp >> 2) * 64;
    const int gr = lane >> 2, gc = lane & 3;

    float acc[2][8][4];
    #pragma unroll
    for (int i = 0; i < 2; i++)
        #pragma unroll
        for (int j = 0; j < 8; j++)
            #pragma unroll
            for (int l = 0; l < 4; l++) acc[i][j][l] = 0.f;

    const unsigned* abase = Ap + (size_t)blockIdx.y * KT32 * 2048;
    const unsigned* bbase = Bp + (size_t)blockIdx.x * KT32 * 2048;

    auto CPA = [&](int kt, int st) {
        const unsigned* at = abase + (size_t)kt * 2048;
        const unsigned* bt = bbase + (size_t)kt * 2048;
        #pragma unroll
        for (int i = 0; i < 2; i++) {
            int ch = tid + i * 256;                   // 512 16B chunks (A)
            cp16(&sm[st * H_STAGE + ch * 4], at + ch * 4);
        }
        #pragma unroll
        for (int i = 0; i < 2; i++) {
            int ch = tid + i * 256;                   // 512 16B chunks (B)
            cp16(&sm[st * H_STAGE + 2048 + ch * 4], bt + ch * 4);
        }
        cp_commit();
    };

    auto COMP = [&](int st) {
        const unsigned* base = sm + st * H_STAGE;
        #pragma unroll
        for (int ks = 0; ks < 2; ks++) {
            unsigned a[2][4];
            #pragma unroll
            for (int mt = 0; mt < 2; mt++) {
                const uint4 av = *(const uint4*)&base[ks * 1024 + (wmt + mt) * 128 + gr * 16 + gc * 4];
                a[mt][0] = av.x; a[mt][1] = av.y; a[mt][2] = av.z; a[mt][3] = av.w;
            }
            #pragma unroll
            for (int nt = 0; nt < 8; nt++) {
                int nc = wn + nt * 8 + gr;
                const uint2 bv = *(const uint2*)&base[2048 + ks * 1024 + nc * 8 + gc * 2];
                mma_f16(acc[0][nt], a[0], bv.x, bv.y);
                mma_f16(acc[1][nt], a[1], bv.x, bv.y);
            }
        }
    };

    CPA(0, 0); CPA(1, 1);
    for (int kt = 0; kt < KT32; kt++) {
        if (kt + 1 < KT32) {
            asm volatile("cp.async.wait_group 1;" ::: "memory");
        } else {
            asm volatile("cp.async.wait_group 0;" ::: "memory");
        }
        __syncthreads();
        if (kt + 2 < KT32) CPA(kt + 2, (kt + 2) % 3);
        COMP(kt % 3);
    }

    #pragma unroll
    for (int mt = 0; mt < 2; mt++) {
        #pragma unroll
        for (int nt = 0; nt < 8; nt++) {
            int r  = row0 + (wmt + mt) * 16 + gr;
            int cc = col0 + wn + nt * 8 + gc * 2;
            float v0 = acc[mt][nt][0], v1 = acc[mt][nt][1];
            float v2 = acc[mt][nt][2], v3 = acc[mt][nt][3];
            if (cc < relu_limit) {
                v0 = fmaxf(v0, 0.f); v1 = fmaxf(v1, 0.f);
                v2 = fmaxf(v2, 0.f); v3 = fmaxf(v3, 0.f);
            }
            *(float2*)&C[(size_t)r * N + cc]       = make_float2(v0, v1);
            *(float2*)&C[(size_t)(r + 8) * N + cc] = make_float2(v2, v3);
        }
    }
}

// ---------------- prep: Wqkv fp16 fragment-major (B layout) -----------------
// pack (tile, ks, n, gc): halves W[k0][n],W[k0+1][n],W[k0+8][n],W[k0+9][n]
__global__ void prep_wqkv_h(const float* __restrict__ Wq, const float* __restrict__ Wk,
                            const float* __restrict__ Wv) {
    int i = blockIdx.x * 256 + threadIdx.x;     // 393216 uint2 packs
    int tile = i >> 10, inner = i & 1023;
    int ks = inner >> 9, rem = inner & 511;
    int n  = rem >> 2, gcn = rem & 3;
    int bn = tile >> 5, kt = tile & 31;
    int k0 = kt * 32 + ks * 16 + gcn * 2;
    int ng = bn * 128 + n;
    float w0, w1, w2, w3;
    if (ng < 1024) {
        w0 = Wq[(size_t)k0 * 1024 + ng];       w1 = Wq[(size_t)(k0 + 1) * 1024 + ng];
        w2 = Wq[(size_t)(k0 + 8) * 1024 + ng]; w3 = Wq[(size_t)(k0 + 9) * 1024 + ng];
    } else if (ng < 1280) {
        int nn = ng - 1024;
        w0 = Wk[(size_t)k0 * 256 + nn];       w1 = Wk[(size_t)(k0 + 1) * 256 + nn];
        w2 = Wk[(size_t)(k0 + 8) * 256 + nn]; w3 = Wk[(size_t)(k0 + 9) * 256 + nn];
    } else {
        int nn = ng - 1280;
        w0 = Wv[(size_t)k0 * 256 + nn];       w1 = Wv[(size_t)(k0 + 1) * 256 + nn];
        w2 = Wv[(size_t)(k0 + 8) * 256 + nn]; w3 = Wv[(size_t)(k0 + 9) * 256 + nn];
    }
    uint2 o = make_uint2(pack2h(w0, w1), pack2h(w2, w3));
    *(uint2*)&g_WqkvH[(size_t)tile * 2048 + ks * 1024 + n * 8 + gcn * 2] = o;
}

// ---------------- prep: Wo fp16 fragment-major (B layout) -------------------
__global__ void prep_wo_h(const float* __restrict__ Wo) {
    int i = blockIdx.x * 256 + threadIdx.x;     // 262144 uint2 packs
    int tile = i >> 10, inner = i & 1023;
    int ks = inner >> 9, rem = inner & 511;
    int n  = rem >> 2, gcn = rem & 3;
    int bn = tile >> 5, kt = tile & 31;
    int k0 = kt * 32 + ks * 16 + gcn * 2;
    int ng = bn * 128 + n;
    float w0 = Wo[(size_t)k0 * 1024 + ng],       w1 = Wo[(size_t)(k0 + 1) * 1024 + ng];
    float w2 = Wo[(size_t)(k0 + 8) * 1024 + ng], w3 = Wo[(size_t)(k0 + 9) * 1024 + ng];
    uint2 o = make_uint2(pack2h(w0, w1), pack2h(w2, w3));
    *(uint2*)&g_WoH[(size_t)tile * 2048 + ks * 1024 + n * 8 + gcn * 2] = o;
}

// ---------------- conv: hs fp16 fragment-major (A layout) -------------------
__global__ void conv_hs_h(const float* __restrict__ hs) {
    int i = blockIdx.x * 256 + threadIdx.x;     // 524288 uint4 packs
    int tile = i >> 9, inner = i & 511;
    int ks = inner >> 8, rem = inner & 255;
    int rblk = rem >> 5, r5 = rem & 31;
    int grr = r5 >> 2, gcn = r5 & 3;
    int bm = tile >> 5, kt = tile & 31;
    int r  = bm * 128 + rblk * 16 + grr;
    int c0 = kt * 32 + ks * 16 + gcn * 2;
    float2 p00 = *(const float2*)&hs[(size_t)r * HID + c0];
    float2 p10 = *(const float2*)&hs[(size_t)(r + 8) * HID + c0];
    float2 p01 = *(const float2*)&hs[(size_t)r * HID + c0 + 8];
    float2 p11 = *(const float2*)&hs[(size_t)(r + 8) * HID + c0 + 8];
    uint4 o = make_uint4(pack2h(p00.x, p00.y), pack2h(p10.x, p10.y),
                         pack2h(p01.x, p01.y), pack2h(p11.x, p11.y));
    *(uint4*)&g_hstH[(size_t)tile * 2048 + ks * 1024 + rblk * 128 + grr * 16 + gcn * 4] = o;
}

// ---------------- fused gate: lg = logsigmoid((hs@Wg1)@Wg2 + b)/16 ---------
__global__ void __launch_bounds__(256) gate_fused(const float* __restrict__ hs,
                                                  const float* __restrict__ Wg1,
                                                  const float* __restrict__ Wg2,
                                                  const float* __restrict__ bg2) {
    __shared__ float hs_s[32][128];
    __shared__ float w1_s[128][16];
    __shared__ float glow_s[32][16];
    __shared__ float w2_s[16][256];

    const int tid = threadIdx.x;
    const int row0 = blockIdx.x * 32;
    const int rowA = tid >> 4;
    const int col  = tid & 15;

    #pragma unroll
    for (int i = tid; i < 4096; i += 256)
        w2_s[i >> 8][i & 255] = Wg2[i];

    float acc0 = 0.f, acc1 = 0.f;
    for (int kt = 0; kt < 8; kt++) {
        __syncthreads();
        #pragma unroll
        for (int i = 0; i < 4; i++) {
            int ch = tid + i * 256;
            int r = ch >> 5, cc = (ch & 31) * 4;
            *(float4*)&hs_s[r][cc] = *(const float4*)&hs[(size_t)(row0 + r) * HID + kt * 128 + cc];
        }
        #pragma unroll
        for (int i = 0; i < 2; i++) {
            int ch = tid + i * 256;
            int kk = ch >> 2, cc = (ch & 3) * 4;
            *(float4*)&w1_s[kk][cc] = *(const float4*)&Wg1[(size_t)(kt * 128 + kk) * 16 + cc];
        }
        __syncthreads();
        #pragma unroll 8
        for (int k = 0; k < 128; k++) {
            float w = w1_s[k][col];
            acc0 = fmaf(hs_s[rowA][k], w, acc0);
            acc1 = fmaf(hs_s[rowA + 16][k], w, acc1);
        }
    }
    glow_s[rowA][col]      = acc0;
    glow_s[rowA + 16][col] = acc1;
    __syncthreads();

    const int c = tid;
    const float bias = bg2[c];
    #pragma unroll 4
    for (int r = 0; r < 32; r++) {
        float x = bias;
        #pragma unroll
        for (int j = 0; j < 16; j++) x = fmaf(glow_s[r][j], w2_s[j][c], x);
        float ls = fminf(x, 0.f) - log1pf(__expf(-fabsf(x)));
        g_lg[(size_t)(row0 + r) * 256 + c] = ls * 0.0625f;
    }
}

// ---------------- Phase A: cumsum; be=exp(b)/8 in place; scale k -----------
__global__ void __launch_bounds__(64) phaseA_kernel() {
    const int c   = blockIdx.x & 31;
    const int grp = blockIdx.x >> 5;
    const int b = grp >> 2, hk = grp & 3;
    const int d = threadIdx.x;
    float bacc = 0.f;
    const size_t row0 = (size_t)b * TT + c * 64;
    for (int t0 = 0; t0 < 64; t0 += 8) {
        float lg8[8], kv8[8];
        #pragma unroll
        for (int i = 0; i < 8; i++)
            lg8[i] = g_lg[(row0 + t0 + i) * 256 + hk * 64 + d];
        #pragma unroll
        for (int i = 0; i < 8; i++)
            kv8[i] = g_qkv[(row0 + t0 + i) * NQKV + 1024 + hk * 64 + d];
        #pragma unroll
        for (int i = 0; i < 8; i++) {
            bacc += lg8[i];
            g_lg[(row0 + t0 + i) * 256 + hk * 64 + d] = __expf(bacc) * 0.125f;
            g_qkv[(row0 + t0 + i) * NQKV + 1024 + hk * 64 + d] = kv8[i] * __expf(-bacc);
        }
    }
    g_dl[(grp * 32 + c) * 64 + d] = __expf(bacc);
}

// ---------------- Phase B: propagate states (cp.async double-buffered) -----
__global__ void __launch_bounds__(128) phaseB_kernel() {
    const int grp = blockIdx.x >> 3;
    const int vc  = blockIdx.x & 7;
    const int b = grp >> 2, hk = grp & 3;
    const int tid = threadIdx.x;
    const int v  = tid & 7;
    const int kg = tid >> 3;
    __shared__ __align__(16) float ke_s[2][64][64];
    __shared__ __align__(16) float v_s[2][64][8];
    float S0 = 0.f, S1 = 0.f, S2 = 0.f, S3 = 0.f;

    const size_t kbase = 1024 + hk * 64;
    const size_t vbase = 1280 + hk * 64 + vc * 8;

    auto ISSUE = [&](int c, int st) {
        const size_t row0 = (size_t)b * TT + c * 64;
        #pragma unroll
        for (int i = 0; i < 8; i++) {
            int idx = tid + i * 128;
            int t = idx >> 4, dq = idx & 15;
            cp16(&ke_s[st][t][dq * 4], &g_qkv[(row0 + t) * NQKV + kbase + dq * 4]);
        }
        {
            int t = tid >> 1, q4 = tid & 1;
            cp16(&v_s[st][t][q4 * 4], &g_qkv[(row0 + t) * NQKV + vbase + q4 * 4]);
        }
        cp_commit();
    };

    ISSUE(0, 0);

    for (int c = 0; c < NCHUNK; c++) {
        if (c + 1 < NCHUNK) {
            ISSUE(c + 1, (c + 1) & 1);
            asm volatile("cp.async.wait_group 1;" ::: "memory");
        } else {
            asm volatile("cp.async.wait_group 0;" ::: "memory");
        }
        __syncthreads();

        const int st = c & 1;
        const size_t sb_ = ((size_t)(grp * 32 + c) * 64 + kg * 4) * 64 + vc * 8 + v;
        g_S[sb_]       = S0;
        g_S[sb_ + 64]  = S1;
        g_S[sb_ + 128] = S2;
        g_S[sb_ + 192] = S3;

        float Pa0 = 0.f, Pa1 = 0.f, Pa2 = 0.f, Pa3 = 0.f;
        float Pb0 = 0.f, Pb1 = 0.f, Pb2 = 0.f, Pb3 = 0.f;
        #pragma unroll 4
        for (int t = 0; t < 64; t += 2) {
            const float4 ka = ((const float4*)ke_s[st][t])[kg];
            const float  va = v_s[st][t][v];
            Pa0 = fmaf(ka.x, va, Pa0);
            Pa1 = fmaf(ka.y, va, Pa1);
            Pa2 = fmaf(ka.z, va, Pa2);
            Pa3 = fmaf(ka.w, va, Pa3);
            const float4 kb = ((const float4*)ke_s[st][t + 1])[kg];
            const float  vb = v_s[st][t + 1][v];
            Pb0 = fmaf(kb.x, vb, Pb0);
            Pb1 = fmaf(kb.y, vb, Pb1);
            Pb2 = fmaf(kb.z, vb, Pb2);
            Pb3 = fmaf(kb.w, vb, Pb3);
        }
        const float4 dl4 = *(const float4*)&g_dl[(grp * 32 + c) * 64 + kg * 4];
        S0 = dl4.x * (S0 + Pa0 + Pb0);
        S1 = dl4.y * (S1 + Pa1 + Pb1);
        S2 = dl4.z * (S2 + Pa2 + Pb2);
        S3 = dl4.w * (S3 + Pa3 + Pb3);
        __syncthreads();
    }
}

// ---------------- Phase C: per (grp,head,chunk); epilogue -> fp16 A layout --
#define PC_LD 65
__global__ void __launch_bounds__(256) phaseC_kernel(const float* __restrict__ gnw) {
    extern __shared__ unsigned smc[];
    unsigned* qe  = smc;
    unsigned* keT = smc + 64 * PC_LD;
    unsigned* vs  = smc + 2 * 64 * PC_LD;
    unsigned* Ss  = smc + 3 * 64 * PC_LD;
    __shared__ float rs[64][2];

    const int c   = blockIdx.x & 31;
    const int h   = (blockIdx.x >> 5) & 3;
    const int grp = blockIdx.x >> 7;
    const int b = grp >> 2, hk = grp & 3;
    const int tid  = threadIdx.x;
    const int lane = tid & 31;
    const int warp = tid >> 5;
    const int wm = (warp & 3) * 16;
    const int wn = (warp >> 2) * 32;
    const int gr = lane >> 2, gc = lane & 3;
    const size_t row0 = (size_t)b * TT + c * 64;

    for (int i = tid; i < 4096; i += 256) {
        int t = i >> 6, d = i & 63;
        float qv = g_qkv[(row0 + t) * NQKV + hk * 256 + h * 64 + d]
                 * g_lg[(row0 + t) * 256 + hk * 64 + d];
        qe [t * PC_LD + d] = f2tf(qv);
        keT[d * PC_LD + t] = f2tf(g_qkv[(row0 + t) * NQKV + 1024 + hk * 64 + d]);
        vs [t * PC_LD + d] = f2tf(g_qkv[(row0 + t) * NQKV + 1280 + hk * 64 + d]);
        Ss [t * PC_LD + d] = f2tf(g_S[((size_t)(grp * 32 + c) * 64 + t) * 64 + d]);
    }
    __syncthreads();

    float accA[4][4];
    #pragma unroll
    for (int j = 0; j < 4; j++)
        #pragma unroll
        for (int l = 0; l < 4; l++) accA[j][l] = 0.f;
    const int rm = wm + gr;
    #pragma unroll
    for (int ks = 0; ks < 8; ks++) {
        int cb = ks * 8 + gc;
        unsigned a[4];
        a[0] = qe[rm * PC_LD + cb];
        a[1] = qe[(rm + 8) * PC_LD + cb];
        a[2] = qe[rm * PC_LD + cb + 4];
        a[3] = qe[(rm + 8) * PC_LD + cb + 4];
        #pragma unroll
        for (int nt = 0; nt < 4; nt++) {
            int nc = wn + nt * 8 + gr;
            unsigned b0 = keT[cb * PC_LD + nc];
            unsigned b1 = keT[(cb + 4) * PC_LD + nc];
            mma_tf32(accA[nt], a, b0, b1);
        }
    }
    __syncthreads();
    #pragma unroll
    for (int nt = 0; nt < 4; nt++) {
        int s0 = wn + nt * 8 + gc * 2;
        keT[rm * PC_LD + s0]           = f2tf(s0     <= rm     ? accA[nt][0] : 0.f);
        keT[rm * PC_LD + s0 + 1]       = f2tf(s0 + 1 <= rm     ? accA[nt][1] : 0.f);
        keT[(rm + 8) * PC_LD + s0]     = f2tf(s0     <= rm + 8 ? accA[nt][2] : 0.f);
        keT[(rm + 8) * PC_LD + s0 + 1] = f2tf(s0 + 1 <= rm + 8 ? accA[nt][3] : 0.f);
    }
    __syncthreads();

    float acc[4][4];
    #pragma unroll
    for (int j = 0; j < 4; j++)
        #pragma unroll
        for (int l = 0; l < 4; l++) acc[j][l] = 0.f;
    #pragma unroll
    for (int ks = 0; ks < 8; ks++) {
        int cb = ks * 8 + gc;
        unsigned a[4];
        a[0] = keT[rm * PC_LD + cb];
        a[1] = keT[(rm + 8) * PC_LD + cb];
        a[2] = keT[rm * PC_LD + cb + 4];
        a[3] = keT[(rm + 8) * PC_LD + cb + 4];
        #pragma unroll
        for (int nt = 0; nt < 4; nt++) {
            int nc = wn + nt * 8 + gr;
            unsigned b0 = vs[cb * PC_LD + nc];
            unsigned b1 = vs[(cb + 4) * PC_LD + nc];
            mma_tf32(acc[nt], a, b0, b1);
        }
    }
    #pragma unroll
    for (int ks = 0; ks < 8; ks++) {
        int cb = ks * 8 + gc;
        unsigned a[4];
        a[0] = qe[rm * PC_LD + cb];
        a[1] = qe[(rm + 8) * PC_LD + cb];
        a[2] = qe[rm * PC_LD + cb + 4];
        a[3] = qe[(rm + 8) * PC_LD + cb + 4];
        #pragma unroll
        for (int nt = 0; nt < 4; nt++) {
            int nc = wn + nt * 8 + gr;
            unsigned b0 = Ss[cb * PC_LD + nc];
            unsigned b1 = Ss[(cb + 4) * PC_LD + nc];
            mma_tf32(acc[nt], a, b0, b1);
        }
    }

    float ss0 = 0.f, ss1 = 0.f;
    #pragma unroll
    for (int nt = 0; nt < 4; nt++) {
        ss0 += acc[nt][0] * acc[nt][0] + acc[nt][1] * acc[nt][1];
        ss1 += acc[nt][2] * acc[nt][2] + acc[nt][3] * acc[nt][3];
    }
    ss0 += __shfl_xor_sync(0xffffffffu, ss0, 1);
    ss0 += __shfl_xor_sync(0xffffffffu, ss0, 2);
    ss1 += __shfl_xor_sync(0xffffffffu, ss1, 1);
    ss1 += __shfl_xor_sync(0xffffffffu, ss1, 2);
    if (gc == 0) {
        rs[rm][warp >> 2]     = ss0;
        rs[rm + 8][warp >> 2] = ss1;
    }
    __syncthreads();
    float r0 = rsqrtf((rs[rm][0] + rs[rm][1]) * (1.f / 64.f) + 1e-6f);
    float r1 = rsqrtf((rs[rm + 8][0] + rs[rm + 8][1]) * (1.f / 64.f) + 1e-6f);

    const int rowg = (int)row0 + rm;
    const int cbase = (hk * 4 + h) * 64;
    #pragma unroll
    for (int nt = 0; nt < 4; nt++) {
        int cl = wn + nt * 8 + gc * 2;
        int colg = cbase + cl;
        float gw0 = gnw[cl], gw1 = gnw[cl + 1];
        g_oattnH[aperm16w(rowg, colg)] =
            pack2h(acc[nt][0] * r0 * gw0, acc[nt][1] * r0 * gw1);
        g_oattnH[aperm16w(rowg + 8, colg)] =
            pack2h(acc[nt][2] * r1 * gw0, acc[nt][3] * r1 * gw1);
    }
}

// ---------------- launch -----------------------------------------------------
extern "C" void kernel_launch(void* const* d_in, const int* in_sizes, int n_in,
                              void* d_out, int out_size) {
    const float* hs  = (const float*)d_in[0];
    const float* Wq  = (const float*)d_in[1];
    const float* Wk  = (const float*)d_in[2];
    const float* Wv  = (const float*)d_in[3];
    const float* Wo  = (const float*)d_in[4];
    const float* Wg1 = (const float*)d_in[5];
    const float* Wg2 = (const float*)d_in[6];
    const float* bg2 = (const float*)d_in[7];
    const float* gnw = (const float*)d_in[8];
    float* out = (float*)d_out;

    unsigned *phstH, *poattnH, *pwqkvH, *pwoH;
    float *pqkv;
    cudaGetSymbolAddress((void**)&phstH,   g_hstH);
    cudaGetSymbolAddress((void**)&pqkv,    g_qkv);
    cudaGetSymbolAddress((void**)&poattnH, g_oattnH);
    cudaGetSymbolAddress((void**)&pwqkvH,  g_WqkvH);
    cudaGetSymbolAddress((void**)&pwoH,    g_WoH);

    cudaFuncSetAttribute(phaseC_kernel,
                         cudaFuncAttributeMaxDynamicSharedMemorySize,
                         4 * 64 * PC_LD * 4);
    cudaFuncSetAttribute(mma_gemm16,
                         cudaFuncAttributeMaxDynamicSharedMemorySize,
                         HSMEM_WORDS * 4);

    // side stream + fork/join events (created once, outside graph capture)
    static cudaStream_t s1 = nullptr;
    static cudaEvent_t evFork = nullptr, evJoin = nullptr;
    if (!s1) {
        cudaStreamCreateWithFlags(&s1, cudaStreamNonBlocking);
        cudaEventCreateWithFlags(&evFork, cudaEventDisableTiming);
        cudaEventCreateWithFlags(&evJoin, cudaEventDisableTiming);
    }

    // fork: gate + Wo prep run concurrently with main chain
    cudaEventRecord(evFork, 0);
    cudaStreamWaitEvent(s1, evFork, 0);
    gate_fused<<<MROWS / 32, 256, 0, s1>>>(hs, Wg1, Wg2, bg2);
    prep_wo_h<<<1024, 256, 0, s1>>>(Wo);
    cudaEventRecord(evJoin, s1);

    // main chain
    prep_wqkv_h<<<1536, 256>>>(Wq, Wk, Wv);
    conv_hs_h<<<2048, 256>>>(hs);
    mma_gemm16<<<dim3(NQKV / 128, MROWS / 128), 256, HSMEM_WORDS * 4>>>(
        phstH, pwqkvH, pqkv, NQKV, 1280);

    // join: phaseA needs g_lg; Wo GEMM needs g_WoH
    cudaStreamWaitEvent(0, evJoin, 0);

    // chunked GLA
    phaseA_kernel<<<8 * NCHUNK, 64>>>();
    phaseB_kernel<<<64, 128>>>();
    phaseC_kernel<<<8 * 4 * NCHUNK, 256, 4 * 64 * PC_LD * 4>>>(gnw);

    // out = oattn @ Wo
    mma_gemm16<<<dim3(HID / 128, MROWS / 128), 256, HSMEM_WORDS * 4>>>(
        poattnH, pwoH, out, HID, 0);
}

// round 16
// speedup vs baseline: 1.5332x; 1.1390x over previous
#include <cuda_runtime.h>
#include <cuda_fp16.h>
#include <math.h>

#define BB   2
#define TT   2048
#define HID  1024
#define HH   16
#define HKV  4
#define MROWS  (BB*TT)          // 4096
#define NQKV   1536             // q(1024) | k(256) | v(256)
#define QCOLS  1024
#define NCHUNK 32               // T / 64
#define KT32   32               // K/32 tiles (K=1024)

// ---------------- scratch (device globals; no allocation) ------------------
__device__ unsigned g_hstH[MROWS * HID / 2];     // hs fp16, fragment-major (A)
__device__ float    g_qkv[MROWS * NQKV];         // [relu(q)|relu(k)->ke|v] fp32 row-major
__device__ float    g_lg[MROWS * 256];           // log decay -> be=exp(b)*0.125
__device__ unsigned g_oattnH[MROWS * QCOLS / 2]; // attention out fp16, fragment-major (A)
__device__ unsigned g_WqkvH[HID * NQKV / 2];     // [Wq|Wk|Wv] fp16 fragment-major (B)
__device__ unsigned g_WoH[QCOLS * HID / 2];      // Wo fp16 fragment-major (B)
__device__ float    g_S[8 * NCHUNK * 64 * 64];   // per-chunk entering states
__device__ float    g_dl[8 * NCHUNK * 64];       // exp(b_last)

// ---------------- helpers ----------------------------------------------------
__device__ __forceinline__ void mma_f16(float* c, const unsigned* a,
                                        unsigned b0, unsigned b1) {
    asm volatile(
        "mma.sync.aligned.m16n8k16.row.col.f32.f16.f16.f32 "
        "{%0,%1,%2,%3},{%4,%5,%6,%7},{%8,%9},{%0,%1,%2,%3};"
        : "+f"(c[0]), "+f"(c[1]), "+f"(c[2]), "+f"(c[3])
        : "r"(a[0]), "r"(a[1]), "r"(a[2]), "r"(a[3]), "r"(b0), "r"(b1));
}
__device__ __forceinline__ unsigned pack2h(float lo, float hi) {
    __half2 h = __floats2half2_rn(lo, hi);
    return *(unsigned*)&h;
}
__device__ __forceinline__ void cp16(void* smem, const void* g) {
    unsigned s = (unsigned)__cvta_generic_to_shared(smem);
    asm volatile("cp.async.cg.shared.global [%0], [%1], 16;" :: "r"(s), "l"(g) : "memory");
}
__device__ __forceinline__ void cp_commit() {
    asm volatile("cp.async.commit_group;" ::: "memory");
}

// word (half-pair) index of (r, c[even]) in the fp16 fragment-major A layout
__device__ __forceinline__ size_t aperm16w(int r, int c) {
    int bm = r >> 7, rin = r & 127;
    int kt = c >> 5, cin = c & 31;
    int ks = cin >> 4, cw = cin & 15;
    int w8 = cw >> 3, c8 = cw & 7;
    int gcn = c8 >> 1;
    int rblk = rin >> 4, r16 = rin & 15;
    int grr = r16 & 7, rb = r16 >> 3;
    return ((size_t)(bm * KT32 + kt)) * 2048 +
           (size_t)(ks * 1024 + rblk * 128 + grr * 16 + gcn * 4 + w8 * 2 + rb);
}

// ---------------- fp16 fragment-major GEMM: C = act(A @ B) ------------------
#define H_STAGE 4096
#define HSMEM_WORDS (3 * H_STAGE)

__global__ void __launch_bounds__(256, 2) mma_gemm16(const unsigned* __restrict__ Ap,
                                                     const unsigned* __restrict__ Bp,
                                                     float* __restrict__ C,
                                                     int N, int relu_limit) {
    extern __shared__ unsigned sm[];

    const int tid  = threadIdx.x;
    const int lane = tid & 31;
    const int warp = tid >> 5;
    const int row0 = blockIdx.y * 128;
    const int col0 = blockIdx.x * 128;
    const int wmt = (warp & 3) * 2;
    const int wn  = (warp >> 2) * 64;
    const int gr = lane >> 2, gc = lane & 3;

    float acc[2][8][4];
    #pragma unroll
    for (int i = 0; i < 2; i++)
        #pragma unroll
        for (int j = 0; j < 8; j++)
            #pragma unroll
            for (int l = 0; l < 4; l++) acc[i][j][l] = 0.f;

    const unsigned* abase = Ap + (size_t)blockIdx.y * KT32 * 2048;
    const unsigned* bbase = Bp + (size_t)blockIdx.x * KT32 * 2048;

    auto CPA = [&](int kt, int st) {
        const unsigned* at = abase + (size_t)kt * 2048;
        const unsigned* bt = bbase + (size_t)kt * 2048;
        #pragma unroll
        for (int i = 0; i < 2; i++) {
            int ch = tid + i * 256;
            cp16(&sm[st * H_STAGE + ch * 4], at + ch * 4);
        }
        #pragma unroll
        for (int i = 0; i < 2; i++) {
            int ch = tid + i * 256;
            cp16(&sm[st * H_STAGE + 2048 + ch * 4], bt + ch * 4);
        }
        cp_commit();
    };

    auto COMP = [&](int st) {
        const unsigned* base = sm + st * H_STAGE;
        #pragma unroll
        for (int ks = 0; ks < 2; ks++) {
            unsigned a[2][4];
            #pragma unroll
            for (int mt = 0; mt < 2; mt++) {
                const uint4 av = *(const uint4*)&base[ks * 1024 + (wmt + mt) * 128 + gr * 16 + gc * 4];
                a[mt][0] = av.x; a[mt][1] = av.y; a[mt][2] = av.z; a[mt][3] = av.w;
            }
            #pragma unroll
            for (int nt = 0; nt < 8; nt++) {
                int nc = wn + nt * 8 + gr;
                const uint2 bv = *(const uint2*)&base[2048 + ks * 1024 + nc * 8 + gc * 2];
                mma_f16(acc[0][nt], a[0], bv.x, bv.y);
                mma_f16(acc[1][nt], a[1], bv.x, bv.y);
            }
        }
    };

    CPA(0, 0); CPA(1, 1);
    for (int kt = 0; kt < KT32; kt++) {
        if (kt + 1 < KT32) {
            asm volatile("cp.async.wait_group 1;" ::: "memory");
        } else {
            asm volatile("cp.async.wait_group 0;" ::: "memory");
        }
        __syncthreads();
        if (kt + 2 < KT32) CPA(kt + 2, (kt + 2) % 3);
        COMP(kt % 3);
    }

    #pragma unroll
    for (int mt = 0; mt < 2; mt++) {
        #pragma unroll
        for (int nt = 0; nt < 8; nt++) {
            int r  = row0 + (wmt + mt) * 16 + gr;
            int cc = col0 + wn + nt * 8 + gc * 2;
            float v0 = acc[mt][nt][0], v1 = acc[mt][nt][1];
            float v2 = acc[mt][nt][2], v3 = acc[mt][nt][3];
            if (cc < relu_limit) {
                v0 = fmaxf(v0, 0.f); v1 = fmaxf(v1, 0.f);
                v2 = fmaxf(v2, 0.f); v3 = fmaxf(v3, 0.f);
            }
            *(float2*)&C[(size_t)r * N + cc]       = make_float2(v0, v1);
            *(float2*)&C[(size_t)(r + 8) * N + cc] = make_float2(v2, v3);
        }
    }
}

// ---------------- prep: Wqkv fp16 fragment-major (B layout) -----------------
__global__ void prep_wqkv_h(const float* __restrict__ Wq, const float* __restrict__ Wk,
                            const float* __restrict__ Wv) {
    int i = blockIdx.x * 256 + threadIdx.x;     // 393216 uint2 packs
    int tile = i >> 10, inner = i & 1023;
    int ks = inner >> 9, rem = inner & 511;
    int n  = rem >> 2, gcn = rem & 3;
    int bn = tile >> 5, kt = tile & 31;
    int k0 = kt * 32 + ks * 16 + gcn * 2;
    int ng = bn * 128 + n;
    float w0, w1, w2, w3;
    if (ng < 1024) {
        w0 = Wq[(size_t)k0 * 1024 + ng];       w1 = Wq[(size_t)(k0 + 1) * 1024 + ng];
        w2 = Wq[(size_t)(k0 + 8) * 1024 + ng]; w3 = Wq[(size_t)(k0 + 9) * 1024 + ng];
    } else if (ng < 1280) {
        int nn = ng - 1024;
        w0 = Wk[(size_t)k0 * 256 + nn];       w1 = Wk[(size_t)(k0 + 1) * 256 + nn];
        w2 = Wk[(size_t)(k0 + 8) * 256 + nn]; w3 = Wk[(size_t)(k0 + 9) * 256 + nn];
    } else {
        int nn = ng - 1280;
        w0 = Wv[(size_t)k0 * 256 + nn];       w1 = Wv[(size_t)(k0 + 1) * 256 + nn];
        w2 = Wv[(size_t)(k0 + 8) * 256 + nn]; w3 = Wv[(size_t)(k0 + 9) * 256 + nn];
    }
    uint2 o = make_uint2(pack2h(w0, w1), pack2h(w2, w3));
    *(uint2*)&g_WqkvH[(size_t)tile * 2048 + ks * 1024 + n * 8 + gcn * 2] = o;
}

// ---------------- prep: Wo fp16 fragment-major (B layout) -------------------
__global__ void prep_wo_h(const float* __restrict__ Wo) {
    int i = blockIdx.x * 256 + threadIdx.x;     // 262144 uint2 packs
    int tile = i >> 10, inner = i & 1023;
    int ks = inner >> 9, rem = inner & 511;
    int n  = rem >> 2, gcn = rem & 3;
    int bn = tile >> 5, kt = tile & 31;
    int k0 = kt * 32 + ks * 16 + gcn * 2;
    int ng = bn * 128 + n;
    float w0 = Wo[(size_t)k0 * 1024 + ng],       w1 = Wo[(size_t)(k0 + 1) * 1024 + ng];
    float w2 = Wo[(size_t)(k0 + 8) * 1024 + ng], w3 = Wo[(size_t)(k0 + 9) * 1024 + ng];
    uint2 o = make_uint2(pack2h(w0, w1), pack2h(w2, w3));
    *(uint2*)&g_WoH[(size_t)tile * 2048 + ks * 1024 + n * 8 + gcn * 2] = o;
}

// ---------------- conv: hs fp16 fragment-major (A layout) -------------------
__global__ void conv_hs_h(const float* __restrict__ hs) {
    int i = blockIdx.x * 256 + threadIdx.x;     // 524288 uint4 packs
    int tile = i >> 9, inner = i & 511;
    int ks = inner >> 8, rem = inner & 255;
    int rblk = rem >> 5, r5 = rem & 31;
    int grr = r5 >> 2, gcn = r5 & 3;
    int bm = tile >> 5, kt = tile & 31;
    int r  = bm * 128 + rblk * 16 + grr;
    int c0 = kt * 32 + ks * 16 + gcn * 2;
    float2 p00 = *(const float2*)&hs[(size_t)r * HID + c0];
    float2 p10 = *(const float2*)&hs[(size_t)(r + 8) * HID + c0];
    float2 p01 = *(const float2*)&hs[(size_t)r * HID + c0 + 8];
    float2 p11 = *(const float2*)&hs[(size_t)(r + 8) * HID + c0 + 8];
    uint4 o = make_uint4(pack2h(p00.x, p00.y), pack2h(p10.x, p10.y),
                         pack2h(p01.x, p01.y), pack2h(p11.x, p11.y));
    *(uint4*)&g_hstH[(size_t)tile * 2048 + ks * 1024 + rblk * 128 + grr * 16 + gcn * 4] = o;
}

// ---------------- fused gate: lg = logsigmoid((hs@Wg1)@Wg2 + b)/16 ---------
__global__ void __launch_bounds__(256) gate_fused(const float* __restrict__ hs,
                                                  const float* __restrict__ Wg1,
                                                  const float* __restrict__ Wg2,
                                                  const float* __restrict__ bg2) {
    __shared__ float hs_s[32][128];
    __shared__ float w1_s[128][16];
    __shared__ float glow_s[32][16];
    __shared__ float w2_s[16][256];

    const int tid = threadIdx.x;
    const int row0 = blockIdx.x * 32;
    const int rowA = tid >> 4;
    const int col  = tid & 15;

    #pragma unroll
    for (int i = tid; i < 4096; i += 256)
        w2_s[i >> 8][i & 255] = Wg2[i];

    float acc0 = 0.f, acc1 = 0.f;
    for (int kt = 0; kt < 8; kt++) {
        __syncthreads();
        #pragma unroll
        for (int i = 0; i < 4; i++) {
            int ch = tid + i * 256;
            int r = ch >> 5, cc = (ch & 31) * 4;
            *(float4*)&hs_s[r][cc] = *(const float4*)&hs[(size_t)(row0 + r) * HID + kt * 128 + cc];
        }
        #pragma unroll
        for (int i = 0; i < 2; i++) {
            int ch = tid + i * 256;
            int kk = ch >> 2, cc = (ch & 3) * 4;
            *(float4*)&w1_s[kk][cc] = *(const float4*)&Wg1[(size_t)(kt * 128 + kk) * 16 + cc];
        }
        __syncthreads();
        #pragma unroll 8
        for (int k = 0; k < 128; k++) {
            float w = w1_s[k][col];
            acc0 = fmaf(hs_s[rowA][k], w, acc0);
            acc1 = fmaf(hs_s[rowA + 16][k], w, acc1);
        }
    }
    glow_s[rowA][col]      = acc0;
    glow_s[rowA + 16][col] = acc1;
    __syncthreads();

    const int c = tid;
    const float bias = bg2[c];
    #pragma unroll 4
    for (int r = 0; r < 32; r++) {
        float x = bias;
        #pragma unroll
        for (int j = 0; j < 16; j++) x = fmaf(glow_s[r][j], w2_s[j][c], x);
        float ls = fminf(x, 0.f) - log1pf(__expf(-fabsf(x)));
        g_lg[(size_t)(row0 + r) * 256 + c] = ls * 0.0625f;
    }
}

// ---------------- Phase A: cumsum; be=exp(b)/8 in place; scale k -----------
__global__ void __launch_bounds__(64) phaseA_kernel() {
    const int c   = blockIdx.x & 31;
    const int grp = blockIdx.x >> 5;
    const int b = grp >> 2, hk = grp & 3;
    const int d = threadIdx.x;
    float bacc = 0.f;
    const size_t row0 = (size_t)b * TT + c * 64;
    for (int t0 = 0; t0 < 64; t0 += 8) {
        float lg8[8], kv8[8];
        #pragma unroll
        for (int i = 0; i < 8; i++)
            lg8[i] = g_lg[(row0 + t0 + i) * 256 + hk * 64 + d];
        #pragma unroll
        for (int i = 0; i < 8; i++)
            kv8[i] = g_qkv[(row0 + t0 + i) * NQKV + 1024 + hk * 64 + d];
        #pragma unroll
        for (int i = 0; i < 8; i++) {
            bacc += lg8[i];
            g_lg[(row0 + t0 + i) * 256 + hk * 64 + d] = __expf(bacc) * 0.125f;
            g_qkv[(row0 + t0 + i) * NQKV + 1024 + hk * 64 + d] = kv8[i] * __expf(-bacc);
        }
    }
    g_dl[(grp * 32 + c) * 64 + d] = __expf(bacc);
}

// ---------------- Phase B: propagate states (cp.async + 4-way partials) ----
__global__ void __launch_bounds__(128) phaseB_kernel() {
    const int grp = blockIdx.x >> 3;
    const int vc  = blockIdx.x & 7;
    const int b = grp >> 2, hk = grp & 3;
    const int tid = threadIdx.x;
    const int v  = tid & 7;
    const int kg = tid >> 3;
    __shared__ __align__(16) float ke_s[2][64][64];
    __shared__ __align__(16) float v_s[2][64][8];
    float S0 = 0.f, S1 = 0.f, S2 = 0.f, S3 = 0.f;

    const size_t kbase = 1024 + hk * 64;
    const size_t vbase = 1280 + hk * 64 + vc * 8;

    auto ISSUE = [&](int c, int st) {
        const size_t row0 = (size_t)b * TT + c * 64;
        #pragma unroll
        for (int i = 0; i < 8; i++) {
            int idx = tid + i * 128;
            int t = idx >> 4, dq = idx & 15;
            cp16(&ke_s[st][t][dq * 4], &g_qkv[(row0 + t) * NQKV + kbase + dq * 4]);
        }
        {
            int t = tid >> 1, q4 = tid & 1;
            cp16(&v_s[st][t][q4 * 4], &g_qkv[(row0 + t) * NQKV + vbase + q4 * 4]);
        }
        cp_commit();
    };

    ISSUE(0, 0);

    for (int c = 0; c < NCHUNK; c++) {
        if (c + 1 < NCHUNK) {
            ISSUE(c + 1, (c + 1) & 1);
            asm volatile("cp.async.wait_group 1;" ::: "memory");
        } else {
            asm volatile("cp.async.wait_group 0;" ::: "memory");
        }
        __syncthreads();

        const int st = c & 1;
        const size_t sb_ = ((size_t)(grp * 32 + c) * 64 + kg * 4) * 64 + vc * 8 + v;
        g_S[sb_]       = S0;
        g_S[sb_ + 64]  = S1;
        g_S[sb_ + 128] = S2;
        g_S[sb_ + 192] = S3;

        float P[4][4];
        #pragma unroll
        for (int p = 0; p < 4; p++)
            #pragma unroll
            for (int l = 0; l < 4; l++) P[p][l] = 0.f;
        #pragma unroll 2
        for (int t = 0; t < 64; t += 4) {
            #pragma unroll
            for (int p = 0; p < 4; p++) {
                const float4 kk = ((const float4*)ke_s[st][t + p])[kg];
                const float  vv = v_s[st][t + p][v];
                P[p][0] = fmaf(kk.x, vv, P[p][0]);
                P[p][1] = fmaf(kk.y, vv, P[p][1]);
                P[p][2] = fmaf(kk.z, vv, P[p][2]);
                P[p][3] = fmaf(kk.w, vv, P[p][3]);
            }
        }
        const float4 dl4 = *(const float4*)&g_dl[(grp * 32 + c) * 64 + kg * 4];
        S0 = dl4.x * (S0 + (P[0][0] + P[1][0]) + (P[2][0] + P[3][0]));
        S1 = dl4.y * (S1 + (P[0][1] + P[1][1]) + (P[2][1] + P[3][1]));
        S2 = dl4.z * (S2 + (P[0][2] + P[1][2]) + (P[2][2] + P[3][2]));
        S3 = dl4.w * (S3 + (P[0][3] + P[1][3]) + (P[2][3] + P[3][3]));
        __syncthreads();
    }
}

// ---------------- Phase C: fp16 MMAs; per (grp,head,chunk) ------------------
// smem word layout: qew[64][33] | Amw[64][33] | keTw[32][65] | vsw[32][65] | Ssw[32][65]
#define QW 33
#define KW 65
#define PC_WORDS (2 * 64 * QW + 3 * 32 * KW)
__global__ void __launch_bounds__(256) phaseC_kernel(const float* __restrict__ gnw) {
    extern __shared__ unsigned smc[];
    unsigned* qew  = smc;
    unsigned* Amw  = smc + 64 * QW;
    unsigned* keTw = smc + 2 * 64 * QW;
    unsigned* vsw  = keTw + 32 * KW;
    unsigned* Ssw  = vsw + 32 * KW;
    __shared__ float rs[64][2];

    const int c   = blockIdx.x & 31;
    const int h   = (blockIdx.x >> 5) & 3;
    const int grp = blockIdx.x >> 7;
    const int b = grp >> 2, hk = grp & 3;
    const int tid  = threadIdx.x;
    const int lane = tid & 31;
    const int warp = tid >> 5;
    const int wm = (warp & 3) * 16;
    const int wn = (warp >> 2) * 32;
    const int gr = lane >> 2, gc = lane & 3;
    const int rm = wm + gr;
    const size_t row0 = (size_t)b * TT + c * 64;

    // stage: qe (scaled) and keT as half2 words
    for (int i = tid; i < 2048; i += 256) {
        int t = i >> 5, dw = i & 31;
        const float* qrow = &g_qkv[(row0 + t) * NQKV + hk * 256 + h * 64 + dw * 2];
        const float* brow = &g_lg[(row0 + t) * 256 + hk * 64 + dw * 2];
        qew[t * QW + dw] = pack2h(qrow[0] * brow[0], qrow[1] * brow[1]);
        const float2 kk = *(const float2*)&g_qkv[(row0 + t) * NQKV + 1024 + hk * 64 + dw * 2];
        keTw[dw * KW + t] = pack2h(kk.x, kk.y);
    }
    // stage: v and S as k-pair words
    for (int i = tid; i < 2048; i += 256) {
        int sw = i >> 6, d = i & 63;
        vsw[sw * KW + d] = pack2h(g_qkv[(row0 + sw * 2) * NQKV + 1280 + hk * 64 + d],
                                  g_qkv[(row0 + sw * 2 + 1) * NQKV + 1280 + hk * 64 + d]);
        const size_t sb = ((size_t)(grp * 32 + c) * 64 + sw * 2) * 64 + d;
        Ssw[sw * KW + d] = pack2h(g_S[sb], g_S[sb + 64]);
    }
    __syncthreads();

    // A = qe @ keT (fp16 k16 x 4 steps)
    float accA[4][4];
    #pragma unroll
    for (int j = 0; j < 4; j++)
        #pragma unroll
        for (int l = 0; l < 4; l++) accA[j][l] = 0.f;
    #pragma unroll
    for (int ks = 0; ks < 4; ks++) {
        unsigned a[4];
        a[0] = qew[rm * QW + ks * 8 + gc];
        a[1] = qew[(rm + 8) * QW + ks * 8 + gc];
        a[2] = qew[rm * QW + ks * 8 + 4 + gc];
        a[3] = qew[(rm + 8) * QW + ks * 8 + 4 + gc];
        #pragma unroll
        for (int nt = 0; nt < 4; nt++) {
            int nc = wn + nt * 8 + gr;
            unsigned b0 = keTw[(ks * 8 + gc) * KW + nc];
            unsigned b1 = keTw[(ks * 8 + 4 + gc) * KW + nc];
            mma_f16(accA[nt], a, b0, b1);
        }
    }
    // causal mask -> Amw (half2 pairs; s0 is even)
    #pragma unroll
    for (int nt = 0; nt < 4; nt++) {
        int s0 = wn + nt * 8 + gc * 2;
        int sw0 = s0 >> 1;
        Amw[rm * QW + sw0] = pack2h(s0 <= rm ? accA[nt][0] : 0.f,
                                    s0 + 1 <= rm ? accA[nt][1] : 0.f);
        Amw[(rm + 8) * QW + sw0] = pack2h(s0 <= rm + 8 ? accA[nt][2] : 0.f,
                                          s0 + 1 <= rm + 8 ? accA[nt][3] : 0.f);
    }
    __syncthreads();

    // O = Am @ v + qe @ S
    float acc[4][4];
    #pragma unroll
    for (int j = 0; j < 4; j++)
        #pragma unroll
        for (int l = 0; l < 4; l++) acc[j][l] = 0.f;
    #pragma unroll
    for (int ks = 0; ks < 4; ks++) {
        unsigned a[4];
        a[0] = Amw[rm * QW + ks * 8 + gc];
        a[1] = Amw[(rm + 8) * QW + ks * 8 + gc];
        a[2] = Amw[rm * QW + ks * 8 + 4 + gc];
        a[3] = Amw[(rm + 8) * QW + ks * 8 + 4 + gc];
        #pragma unroll
        for (int nt = 0; nt < 4; nt++) {
            int nc = wn + nt * 8 + gr;
            unsigned b0 = vsw[(ks * 8 + gc) * KW + nc];
            unsigned b1 = vsw[(ks * 8 + 4 + gc) * KW + nc];
            mma_f16(acc[nt], a, b0, b1);
        }
    }
    #pragma unroll
    for (int ks = 0; ks < 4; ks++) {
        unsigned a[4];
        a[0] = qew[rm * QW + ks * 8 + gc];
        a[1] = qew[(rm + 8) * QW + ks * 8 + gc];
        a[2] = qew[rm * QW + ks * 8 + 4 + gc];
        a[3] = qew[(rm + 8) * QW + ks * 8 + 4 + gc];
        #pragma unroll
        for (int nt = 0; nt < 4; nt++) {
            int nc = wn + nt * 8 + gr;
            unsigned b0 = Ssw[(ks * 8 + gc) * KW + nc];
            unsigned b1 = Ssw[(ks * 8 + 4 + gc) * KW + nc];
            mma_f16(acc[nt], a, b0, b1);
        }
    }

    // fused RMSNorm
    float ss0 = 0.f, ss1 = 0.f;
    #pragma unroll
    for (int nt = 0; nt < 4; nt++) {
        ss0 += acc[nt][0] * acc[nt][0] + acc[nt][1] * acc[nt][1];
        ss1 += acc[nt][2] * acc[nt][2] + acc[nt][3] * acc[nt][3];
    }
    ss0 += __shfl_xor_sync(0xffffffffu, ss0, 1);
    ss0 += __shfl_xor_sync(0xffffffffu, ss0, 2);
    ss1 += __shfl_xor_sync(0xffffffffu, ss1, 1);
    ss1 += __shfl_xor_sync(0xffffffffu, ss1, 2);
    if (gc == 0) {
        rs[rm][warp >> 2]     = ss0;
        rs[rm + 8][warp >> 2] = ss1;
    }
    __syncthreads();
    float r0 = rsqrtf((rs[rm][0] + rs[rm][1]) * (1.f / 64.f) + 1e-6f);
    float r1 = rsqrtf((rs[rm + 8][0] + rs[rm + 8][1]) * (1.f / 64.f) + 1e-6f);

    const int rowg = (int)row0 + rm;
    const int cbase = (hk * 4 + h) * 64;
    #pragma unroll
    for (int nt = 0; nt < 4; nt++) {
        int cl = wn + nt * 8 + gc * 2;
        int colg = cbase + cl;
        float gw0 = gnw[cl], gw1 = gnw[cl + 1];
        g_oattnH[aperm16w(rowg, colg)] =
            pack2h(acc[nt][0] * r0 * gw0, acc[nt][1] * r0 * gw1);
        g_oattnH[aperm16w(rowg + 8, colg)] =
            pack2h(acc[nt][2] * r1 * gw0, acc[nt][3] * r1 * gw1);
    }
}

// ---------------- launch -----------------------------------------------------
extern "C" void kernel_launch(void* const* d_in, const int* in_sizes, int n_in,
                              void* d_out, int out_size) {
    const float* hs  = (const float*)d_in[0];
    const float* Wq  = (const float*)d_in[1];
    const float* Wk  = (const float*)d_in[2];
    const float* Wv  = (const float*)d_in[3];
    const float* Wo  = (const float*)d_in[4];
    const float* Wg1 = (const float*)d_in[5];
    const float* Wg2 = (const float*)d_in[6];
    const float* bg2 = (const float*)d_in[7];
    const float* gnw = (const float*)d_in[8];
    float* out = (float*)d_out;

    unsigned *phstH, *poattnH, *pwqkvH, *pwoH;
    float *pqkv;
    cudaGetSymbolAddress((void**)&phstH,   g_hstH);
    cudaGetSymbolAddress((void**)&pqkv,    g_qkv);
    cudaGetSymbolAddress((void**)&poattnH, g_oattnH);
    cudaGetSymbolAddress((void**)&pwqkvH,  g_WqkvH);
    cudaGetSymbolAddress((void**)&pwoH,    g_WoH);

    cudaFuncSetAttribute(phaseC_kernel,
                         cudaFuncAttributeMaxDynamicSharedMemorySize,
                         PC_WORDS * 4);
    cudaFuncSetAttribute(mma_gemm16,
                         cudaFuncAttributeMaxDynamicSharedMemorySize,
                         HSMEM_WORDS * 4);

    // side stream + fork/join events (created once, outside graph capture)
    static cudaStream_t s1 = nullptr;
    static cudaEvent_t evFork = nullptr, evJoin = nullptr;
    if (!s1) {
        cudaStreamCreateWithFlags(&s1, cudaStreamNonBlocking);
        cudaEventCreateWithFlags(&evFork, cudaEventDisableTiming);
        cudaEventCreateWithFlags(&evJoin, cudaEventDisableTiming);
    }

    // fork: gate + Wo prep run concurrently with main chain
    cudaEventRecord(evFork, 0);
    cudaStreamWaitEvent(s1, evFork, 0);
    gate_fused<<<MROWS / 32, 256, 0, s1>>>(hs, Wg1, Wg2, bg2);
    prep_wo_h<<<1024, 256, 0, s1>>>(Wo);
    cudaEventRecord(evJoin, s1);

    // main chain
    prep_wqkv_h<<<1536, 256>>>(Wq, Wk, Wv);
    conv_hs_h<<<2048, 256>>>(hs);
    mma_gemm16<<<dim3(NQKV / 128, MROWS / 128), 256, HSMEM_WORDS * 4>>>(
        phstH, pwqkvH, pqkv, NQKV, 1280);

    // join: phaseA needs g_lg; Wo GEMM needs g_WoH
    cudaStreamWaitEvent(0, evJoin, 0);

    // chunked GLA
    phaseA_kernel<<<8 * NCHUNK, 64>>>();
    phaseB_kernel<<<64, 128>>>();
    phaseC_kernel<<<8 * 4 * NCHUNK, 256, PC_WORDS * 4>>>(gnw);

    // out = oattn @ Wo
    mma_gemm16<<<dim3(HID / 128, MROWS / 128), 256, HSMEM_WORDS * 4>>>(
        poattnH, pwoH, out, HID, 0);
}

// round 17
// speedup vs baseline: 1.6143x; 1.0529x over previous
#include <cuda_runtime.h>
#include <cuda_fp16.h>
#include <math.h>

#define BB   2
#define TT   2048
#define HID  1024
#define HH   16
#define HKV  4
#define MROWS  (BB*TT)          // 4096
#define NQKV   1536             // q(1024) | k(256) | v(256)
#define QCOLS  1024
#define NCHUNK 32               // T / 64
#define KT32   32               // K/32 tiles (K=1024)

// ---------------- scratch (device globals; no allocation) ------------------
__device__ unsigned g_hstH[MROWS * HID / 2];     // hs fp16, fragment-major (A)
__device__ float    g_qkv[MROWS * NQKV];         // [relu(q)|relu(k)->ke|v] fp32 row-major
__device__ float    g_lg[MROWS * 256];           // log decay -> be=exp(b)*0.125
__device__ unsigned g_oattnH[MROWS * QCOLS / 2]; // attention out fp16, fragment-major (A)
__device__ unsigned g_WqkvH[HID * NQKV / 2];     // [Wq|Wk|Wv] fp16 fragment-major (B)
__device__ unsigned g_WoH[QCOLS * HID / 2];      // Wo fp16 fragment-major (B)
__device__ float    g_S[8 * NCHUNK * 64 * 64];   // per-chunk entering states
__device__ float    g_dl[8 * NCHUNK * 64];       // exp(b_last)

// ---------------- helpers ----------------------------------------------------
__device__ __forceinline__ void mma_f16(float* c, const unsigned* a,
                                        unsigned b0, unsigned b1) {
    asm volatile(
        "mma.sync.aligned.m16n8k16.row.col.f32.f16.f16.f32 "
        "{%0,%1,%2,%3},{%4,%5,%6,%7},{%8,%9},{%0,%1,%2,%3};"
        : "+f"(c[0]), "+f"(c[1]), "+f"(c[2]), "+f"(c[3])
        : "r"(a[0]), "r"(a[1]), "r"(a[2]), "r"(a[3]), "r"(b0), "r"(b1));
}
__device__ __forceinline__ unsigned pack2h(float lo, float hi) {
    __half2 h = __floats2half2_rn(lo, hi);
    return *(unsigned*)&h;
}
__device__ __forceinline__ void cp16(void* smem, const void* g) {
    unsigned s = (unsigned)__cvta_generic_to_shared(smem);
    asm volatile("cp.async.cg.shared.global [%0], [%1], 16;" :: "r"(s), "l"(g) : "memory");
}
__device__ __forceinline__ void cp_commit() {
    asm volatile("cp.async.commit_group;" ::: "memory");
}

// word (half-pair) index of (r, c[even]) in the fp16 fragment-major A layout
__device__ __forceinline__ size_t aperm16w(int r, int c) {
    int bm = r >> 7, rin = r & 127;
    int kt = c >> 5, cin = c & 31;
    int ks = cin >> 4, cw = cin & 15;
    int w8 = cw >> 3, c8 = cw & 7;
    int gcn = c8 >> 1;
    int rblk = rin >> 4, r16 = rin & 15;
    int grr = r16 & 7, rb = r16 >> 3;
    return ((size_t)(bm * KT32 + kt)) * 2048 +
           (size_t)(ks * 1024 + rblk * 128 + grr * 16 + gcn * 4 + w8 * 2 + rb);
}

// ---------------- fp16 fragment-major GEMM: C = act(A @ B) ------------------
// BM=128, BN=128, BK=64 (two fragment tiles / stage), 3-stage cp.async ring.
#define H_STAGE2 8192
#define HSMEM_WORDS (3 * H_STAGE2)
#define NT2 (KT32 / 2)

__global__ void __launch_bounds__(256, 2) mma_gemm16(const unsigned* __restrict__ Ap,
                                                     const unsigned* __restrict__ Bp,
                                                     float* __restrict__ C,
                                                     int N, int relu_limit) {
    extern __shared__ unsigned sm[];

    const int tid  = threadIdx.x;
    const int lane = tid & 31;
    const int warp = tid >> 5;
    const int row0 = blockIdx.y * 128;
    const int col0 = blockIdx.x * 128;
    const int wmt = (warp & 3) * 2;
    const int wn  = (warp >> 2) * 64;
    const int gr = lane >> 2, gc = lane & 3;

    float acc[2][8][4];
    #pragma unroll
    for (int i = 0; i < 2; i++)
        #pragma unroll
        for (int j = 0; j < 8; j++)
            #pragma unroll
            for (int l = 0; l < 4; l++) acc[i][j][l] = 0.f;

    const unsigned* abase = Ap + (size_t)blockIdx.y * KT32 * 2048;
    const unsigned* bbase = Bp + (size_t)blockIdx.x * KT32 * 2048;

    auto CPA = [&](int kt2, int st) {
        const unsigned* at = abase + (size_t)kt2 * 4096;
        const unsigned* bt = bbase + (size_t)kt2 * 4096;
        #pragma unroll
        for (int i = 0; i < 4; i++) {
            int ch = tid + i * 256;                 // 1024 16B chunks (A: 2 tiles)
            cp16(&sm[st * H_STAGE2 + ch * 4], at + ch * 4);
        }
        #pragma unroll
        for (int i = 0; i < 4; i++) {
            int ch = tid + i * 256;                 // 1024 16B chunks (B: 2 tiles)
            cp16(&sm[st * H_STAGE2 + 4096 + ch * 4], bt + ch * 4);
        }
        cp_commit();
    };

    auto COMP = [&](int st) {
        const unsigned* base = sm + st * H_STAGE2;
        #pragma unroll
        for (int ks = 0; ks < 4; ks++) {
            const int aoff = (ks >> 1) * 2048 + (ks & 1) * 1024;
            unsigned a[2][4];
            #pragma unroll
            for (int mt = 0; mt < 2; mt++) {
                const uint4 av = *(const uint4*)&base[aoff + (wmt + mt) * 128 + gr * 16 + gc * 4];
                a[mt][0] = av.x; a[mt][1] = av.y; a[mt][2] = av.z; a[mt][3] = av.w;
            }
            #pragma unroll
            for (int nt = 0; nt < 8; nt++) {
                int nc = wn + nt * 8 + gr;
                const uint2 bv = *(const uint2*)&base[4096 + aoff + nc * 8 + gc * 2];
                mma_f16(acc[0][nt], a[0], bv.x, bv.y);
                mma_f16(acc[1][nt], a[1], bv.x, bv.y);
            }
        }
    };

    CPA(0, 0); CPA(1, 1);
    for (int kt2 = 0; kt2 < NT2; kt2++) {
        if (kt2 + 1 < NT2) {
            asm volatile("cp.async.wait_group 1;" ::: "memory");
        } else {
            asm volatile("cp.async.wait_group 0;" ::: "memory");
        }
        __syncthreads();
        if (kt2 + 2 < NT2) CPA(kt2 + 2, (kt2 + 2) % 3);
        COMP(kt2 % 3);
    }

    #pragma unroll
    for (int mt = 0; mt < 2; mt++) {
        #pragma unroll
        for (int nt = 0; nt < 8; nt++) {
            int r  = row0 + (wmt + mt) * 16 + gr;
            int cc = col0 + wn + nt * 8 + gc * 2;
            float v0 = acc[mt][nt][0], v1 = acc[mt][nt][1];
            float v2 = acc[mt][nt][2], v3 = acc[mt][nt][3];
            if (cc < relu_limit) {
                v0 = fmaxf(v0, 0.f); v1 = fmaxf(v1, 0.f);
                v2 = fmaxf(v2, 0.f); v3 = fmaxf(v3, 0.f);
            }
            *(float2*)&C[(size_t)r * N + cc]       = make_float2(v0, v1);
            *(float2*)&C[(size_t)(r + 8) * N + cc] = make_float2(v2, v3);
        }
    }
}

// ---------------- merged prep: Wqkv (B layout) + hs (A layout) --------------
__global__ void prep_main(const float* __restrict__ Wq, const float* __restrict__ Wk,
                          const float* __restrict__ Wv, const float* __restrict__ hs) {
    if (blockIdx.x < 1536) {
        // Wqkv fp16 fragment-major (B layout): 393216 uint2 packs
        int i = blockIdx.x * 256 + threadIdx.x;
        int tile = i >> 10, inner = i & 1023;
        int ks = inner >> 9, rem = inner & 511;
        int n  = rem >> 2, gcn = rem & 3;
        int bn = tile >> 5, kt = tile & 31;
        int k0 = kt * 32 + ks * 16 + gcn * 2;
        int ng = bn * 128 + n;
        float w0, w1, w2, w3;
        if (ng < 1024) {
            w0 = Wq[(size_t)k0 * 1024 + ng];       w1 = Wq[(size_t)(k0 + 1) * 1024 + ng];
            w2 = Wq[(size_t)(k0 + 8) * 1024 + ng]; w3 = Wq[(size_t)(k0 + 9) * 1024 + ng];
        } else if (ng < 1280) {
            int nn = ng - 1024;
            w0 = Wk[(size_t)k0 * 256 + nn];       w1 = Wk[(size_t)(k0 + 1) * 256 + nn];
            w2 = Wk[(size_t)(k0 + 8) * 256 + nn]; w3 = Wk[(size_t)(k0 + 9) * 256 + nn];
        } else {
            int nn = ng - 1280;
            w0 = Wv[(size_t)k0 * 256 + nn];       w1 = Wv[(size_t)(k0 + 1) * 256 + nn];
            w2 = Wv[(size_t)(k0 + 8) * 256 + nn]; w3 = Wv[(size_t)(k0 + 9) * 256 + nn];
        }
        uint2 o = make_uint2(pack2h(w0, w1), pack2h(w2, w3));
        *(uint2*)&g_WqkvH[(size_t)tile * 2048 + ks * 1024 + n * 8 + gcn * 2] = o;
    } else {
        // hs fp16 fragment-major (A layout): 524288 uint4 packs
        int i = (blockIdx.x - 1536) * 256 + threadIdx.x;
        int tile = i >> 9, inner = i & 511;
        int ks = inner >> 8, rem = inner & 255;
        int rblk = rem >> 5, r5 = rem & 31;
        int grr = r5 >> 2, gcn = r5 & 3;
        int bm = tile >> 5, kt = tile & 31;
        int r  = bm * 128 + rblk * 16 + grr;
        int c0 = kt * 32 + ks * 16 + gcn * 2;
        float2 p00 = *(const float2*)&hs[(size_t)r * HID + c0];
        float2 p10 = *(const float2*)&hs[(size_t)(r + 8) * HID + c0];
        float2 p01 = *(const float2*)&hs[(size_t)r * HID + c0 + 8];
        float2 p11 = *(const float2*)&hs[(size_t)(r + 8) * HID + c0 + 8];
        uint4 o = make_uint4(pack2h(p00.x, p00.y), pack2h(p10.x, p10.y),
                             pack2h(p01.x, p01.y), pack2h(p11.x, p11.y));
        *(uint4*)&g_hstH[(size_t)tile * 2048 + ks * 1024 + rblk * 128 + grr * 16 + gcn * 4] = o;
    }
}

// ---------------- prep: Wo fp16 fragment-major (B layout) -------------------
__global__ void prep_wo_h(const float* __restrict__ Wo) {
    int i = blockIdx.x * 256 + threadIdx.x;     // 262144 uint2 packs
    int tile = i >> 10, inner = i & 1023;
    int ks = inner >> 9, rem = inner & 511;
    int n  = rem >> 2, gcn = rem & 3;
    int bn = tile >> 5, kt = tile & 31;
    int k0 = kt * 32 + ks * 16 + gcn * 2;
    int ng = bn * 128 + n;
    float w0 = Wo[(size_t)k0 * 1024 + ng],       w1 = Wo[(size_t)(k0 + 1) * 1024 + ng];
    float w2 = Wo[(size_t)(k0 + 8) * 1024 + ng], w3 = Wo[(size_t)(k0 + 9) * 1024 + ng];
    uint2 o = make_uint2(pack2h(w0, w1), pack2h(w2, w3));
    *(uint2*)&g_WoH[(size_t)tile * 2048 + ks * 1024 + n * 8 + gcn * 2] = o;
}

// ---------------- fused gate: lg = logsigmoid((hs@Wg1)@Wg2 + b)/16 ---------
__global__ void __launch_bounds__(256) gate_fused(const float* __restrict__ hs,
                                                  const float* __restrict__ Wg1,
                                                  const float* __restrict__ Wg2,
                                                  const float* __restrict__ bg2) {
    __shared__ float hs_s[32][128];
    __shared__ float w1_s[128][16];
    __shared__ float glow_s[32][16];
    __shared__ float w2_s[16][256];

    const int tid = threadIdx.x;
    const int row0 = blockIdx.x * 32;
    const int rowA = tid >> 4;
    const int col  = tid & 15;

    #pragma unroll
    for (int i = tid; i < 4096; i += 256)
        w2_s[i >> 8][i & 255] = Wg2[i];

    float acc0 = 0.f, acc1 = 0.f;
    for (int kt = 0; kt < 8; kt++) {
        __syncthreads();
        #pragma unroll
        for (int i = 0; i < 4; i++) {
            int ch = tid + i * 256;
            int r = ch >> 5, cc = (ch & 31) * 4;
            *(float4*)&hs_s[r][cc] = *(const float4*)&hs[(size_t)(row0 + r) * HID + kt * 128 + cc];
        }
        #pragma unroll
        for (int i = 0; i < 2; i++) {
            int ch = tid + i * 256;
            int kk = ch >> 2, cc = (ch & 3) * 4;
            *(float4*)&w1_s[kk][cc] = *(const float4*)&Wg1[(size_t)(kt * 128 + kk) * 16 + cc];
        }
        __syncthreads();
        #pragma unroll 8
        for (int k = 0; k < 128; k++) {
            float w = w1_s[k][col];
            acc0 = fmaf(hs_s[rowA][k], w, acc0);
            acc1 = fmaf(hs_s[rowA + 16][k], w, acc1);
        }
    }
    glow_s[rowA][col]      = acc0;
    glow_s[rowA + 16][col] = acc1;
    __syncthreads();

    const int c = tid;
    const float bias = bg2[c];
    #pragma unroll 4
    for (int r = 0; r < 32; r++) {
        float x = bias;
        #pragma unroll
        for (int j = 0; j < 16; j++) x = fmaf(glow_s[r][j], w2_s[j][c], x);
        float ls = fminf(x, 0.f) - log1pf(__expf(-fabsf(x)));
        g_lg[(size_t)(row0 + r) * 256 + c] = ls * 0.0625f;
    }
}

// ---------------- Phase A: cumsum; be=exp(b)/8 in place; scale k -----------
__global__ void __launch_bounds__(64) phaseA_kernel() {
    const int c   = blockIdx.x & 31;
    const int grp = blockIdx.x >> 5;
    const int b = grp >> 2, hk = grp & 3;
    const int d = threadIdx.x;
    float bacc = 0.f;
    const size_t row0 = (size_t)b * TT + c * 64;
    for (int t0 = 0; t0 < 64; t0 += 8) {
        float lg8[8], kv8[8];
        #pragma unroll
        for (int i = 0; i < 8; i++)
            lg8[i] = g_lg[(row0 + t0 + i) * 256 + hk * 64 + d];
        #pragma unroll
        for (int i = 0; i < 8; i++)
            kv8[i] = g_qkv[(row0 + t0 + i) * NQKV + 1024 + hk * 64 + d];
        #pragma unroll
        for (int i = 0; i < 8; i++) {
            bacc += lg8[i];
            g_lg[(row0 + t0 + i) * 256 + hk * 64 + d] = __expf(bacc) * 0.125f;
            g_qkv[(row0 + t0 + i) * NQKV + 1024 + hk * 64 + d] = kv8[i] * __expf(-bacc);
        }
    }
    g_dl[(grp * 32 + c) * 64 + d] = __expf(bacc);
}

// ---------------- Phase B: propagate states (cp.async + 4-way partials) ----
__global__ void __launch_bounds__(128) phaseB_kernel() {
    const int grp = blockIdx.x >> 3;
    const int vc  = blockIdx.x & 7;
    const int b = grp >> 2, hk = grp & 3;
    const int tid = threadIdx.x;
    const int v  = tid & 7;
    const int kg = tid >> 3;
    __shared__ __align__(16) float ke_s[2][64][64];
    __shared__ __align__(16) float v_s[2][64][8];
    float S0 = 0.f, S1 = 0.f, S2 = 0.f, S3 = 0.f;

    const size_t kbase = 1024 + hk * 64;
    const size_t vbase = 1280 + hk * 64 + vc * 8;

    auto ISSUE = [&](int c, int st) {
        const size_t row0 = (size_t)b * TT + c * 64;
        #pragma unroll
        for (int i = 0; i < 8; i++) {
            int idx = tid + i * 128;
            int t = idx >> 4, dq = idx & 15;
            cp16(&ke_s[st][t][dq * 4], &g_qkv[(row0 + t) * NQKV + kbase + dq * 4]);
        }
        {
            int t = tid >> 1, q4 = tid & 1;
            cp16(&v_s[st][t][q4 * 4], &g_qkv[(row0 + t) * NQKV + vbase + q4 * 4]);
        }
        cp_commit();
    };

    ISSUE(0, 0);

    for (int c = 0; c < NCHUNK; c++) {
        if (c + 1 < NCHUNK) {
            ISSUE(c + 1, (c + 1) & 1);
            asm volatile("cp.async.wait_group 1;" ::: "memory");
        } else {
            asm volatile("cp.async.wait_group 0;" ::: "memory");
        }
        __syncthreads();

        const int st = c & 1;
        const size_t sb_ = ((size_t)(grp * 32 + c) * 64 + kg * 4) * 64 + vc * 8 + v;
        g_S[sb_]       = S0;
        g_S[sb_ + 64]  = S1;
        g_S[sb_ + 128] = S2;
        g_S[sb_ + 192] = S3;

        float P[4][4];
        #pragma unroll
        for (int p = 0; p < 4; p++)
            #pragma unroll
            for (int l = 0; l < 4; l++) P[p][l] = 0.f;
        #pragma unroll 2
        for (int t = 0; t < 64; t += 4) {
            #pragma unroll
            for (int p = 0; p < 4; p++) {
                const float4 kk = ((const float4*)ke_s[st][t + p])[kg];
                const float  vv = v_s[st][t + p][v];
                P[p][0] = fmaf(kk.x, vv, P[p][0]);
                P[p][1] = fmaf(kk.y, vv, P[p][1]);
                P[p][2] = fmaf(kk.z, vv, P[p][2]);
                P[p][3] = fmaf(kk.w, vv, P[p][3]);
            }
        }
        const float4 dl4 = *(const float4*)&g_dl[(grp * 32 + c) * 64 + kg * 4];
        S0 = dl4.x * (S0 + (P[0][0] + P[1][0]) + (P[2][0] + P[3][0]));
        S1 = dl4.y * (S1 + (P[0][1] + P[1][1]) + (P[2][1] + P[3][1]));
        S2 = dl4.z * (S2 + (P[0][2] + P[1][2]) + (P[2][2] + P[3][2]));
        S3 = dl4.w * (S3 + (P[0][3] + P[1][3]) + (P[2][3] + P[3][3]));
        __syncthreads();
    }
}

// ---------------- Phase C: fp16 MMAs; per (grp,head,chunk) ------------------
#define QW 33
#define KW 65
#define PC_WORDS (2 * 64 * QW + 3 * 32 * KW)
__global__ void __launch_bounds__(256) phaseC_kernel(const float* __restrict__ gnw) {
    extern __shared__ unsigned smc[];
    unsigned* qew  = smc;
    unsigned* Amw  = smc + 64 * QW;
    unsigned* keTw = smc + 2 * 64 * QW;
    unsigned* vsw  = keTw + 32 * KW;
    unsigned* Ssw  = vsw + 32 * KW;
    __shared__ float rs[64][2];

    const int c   = blockIdx.x & 31;
    const int h   = (blockIdx.x >> 5) & 3;
    const int grp = blockIdx.x >> 7;
    const int b = grp >> 2, hk = grp & 3;
    const int tid  = threadIdx.x;
    const int lane = tid & 31;
    const int warp = tid >> 5;
    const int wm = (warp & 3) * 16;
    const int wn = (warp >> 2) * 32;
    const int gr = lane >> 2, gc = lane & 3;
    const int rm = wm + gr;
    const size_t row0 = (size_t)b * TT + c * 64;

    for (int i = tid; i < 2048; i += 256) {
        int t = i >> 5, dw = i & 31;
        const float* qrow = &g_qkv[(row0 + t) * NQKV + hk * 256 + h * 64 + dw * 2];
        const float* brow = &g_lg[(row0 + t) * 256 + hk * 64 + dw * 2];
        qew[t * QW + dw] = pack2h(qrow[0] * brow[0], qrow[1] * brow[1]);
        const float2 kk = *(const float2*)&g_qkv[(row0 + t) * NQKV + 1024 + hk * 64 + dw * 2];
        keTw[dw * KW + t] = pack2h(kk.x, kk.y);
    }
    for (int i = tid; i < 2048; i += 256) {
        int sw = i >> 6, d = i & 63;
        vsw[sw * KW + d] = pack2h(g_qkv[(row0 + sw * 2) * NQKV + 1280 + hk * 64 + d],
                                  g_qkv[(row0 + sw * 2 + 1) * NQKV + 1280 + hk * 64 + d]);
        const size_t sb = ((size_t)(grp * 32 + c) * 64 + sw * 2) * 64 + d;
        Ssw[sw * KW + d] = pack2h(g_S[sb], g_S[sb + 64]);
    }
    __syncthreads();

    float accA[4][4];
    #pragma unroll
    for (int j = 0; j < 4; j++)
        #pragma unroll
        for (int l = 0; l < 4; l++) accA[j][l] = 0.f;
    #pragma unroll
    for (int ks = 0; ks < 4; ks++) {
        unsigned a[4];
        a[0] = qew[rm * QW + ks * 8 + gc];
        a[1] = qew[(rm + 8) * QW + ks * 8 + gc];
        a[2] = qew[rm * QW + ks * 8 + 4 + gc];
        a[3] = qew[(rm + 8) * QW + ks * 8 + 4 + gc];
        #pragma unroll
        for (int nt = 0; nt < 4; nt++) {
            int nc = wn + nt * 8 + gr;
            unsigned b0 = keTw[(ks * 8 + gc) * KW + nc];
            unsigned b1 = keTw[(ks * 8 + 4 + gc) * KW + nc];
            mma_f16(accA[nt], a, b0, b1);
        }
    }
    #pragma unroll
    for (int nt = 0; nt < 4; nt++) {
        int s0 = wn + nt * 8 + gc * 2;
        int sw0 = s0 >> 1;
        Amw[rm * QW + sw0] = pack2h(s0 <= rm ? accA[nt][0] : 0.f,
                                    s0 + 1 <= rm ? accA[nt][1] : 0.f);
        Amw[(rm + 8) * QW + sw0] = pack2h(s0 <= rm + 8 ? accA[nt][2] : 0.f,
                                          s0 + 1 <= rm + 8 ? accA[nt][3] : 0.f);
    }
    __syncthreads();

    float acc[4][4];
    #pragma unroll
    for (int j = 0; j < 4; j++)
        #pragma unroll
        for (int l = 0; l < 4; l++) acc[j][l] = 0.f;
    #pragma unroll
    for (int ks = 0; ks < 4; ks++) {
        unsigned a[4];
        a[0] = Amw[rm * QW + ks * 8 + gc];
        a[1] = Amw[(rm + 8) * QW + ks * 8 + gc];
        a[2] = Amw[rm * QW + ks * 8 + 4 + gc];
        a[3] = Amw[(rm + 8) * QW + ks * 8 + 4 + gc];
        #pragma unroll
        for (int nt = 0; nt < 4; nt++) {
            int nc = wn + nt * 8 + gr;
            unsigned b0 = vsw[(ks * 8 + gc) * KW + nc];
            unsigned b1 = vsw[(ks * 8 + 4 + gc) * KW + nc];
            mma_f16(acc[nt], a, b0, b1);
        }
    }
    #pragma unroll
    for (int ks = 0; ks < 4; ks++) {
        unsigned a[4];
        a[0] = qew[rm * QW + ks * 8 + gc];
        a[1] = qew[(rm + 8) * QW + ks * 8 + gc];
        a[2] = qew[rm * QW + ks * 8 + 4 + gc];
        a[3] = qew[(rm + 8) * QW + ks * 8 + 4 + gc];
        #pragma unroll
        for (int nt = 0; nt < 4; nt++) {
            int nc = wn + nt * 8 + gr;
            unsigned b0 = Ssw[(ks * 8 + gc) * KW + nc];
            unsigned b1 = Ssw[(ks * 8 + 4 + gc) * KW + nc];
            mma_f16(acc[nt], a, b0, b1);
        }
    }

    float ss0 = 0.f, ss1 = 0.f;
    #pragma unroll
    for (int nt = 0; nt < 4; nt++) {
        ss0 += acc[nt][0] * acc[nt][0] + acc[nt][1] * acc[nt][1];
        ss1 += acc[nt][2] * acc[nt][2] + acc[nt][3] * acc[nt][3];
    }
    ss0 += __shfl_xor_sync(0xffffffffu, ss0, 1);
    ss0 += __shfl_xor_sync(0xffffffffu, ss0, 2);
    ss1 += __shfl_xor_sync(0xffffffffu, ss1, 1);
    ss1 += __shfl_xor_sync(0xffffffffu, ss1, 2);
    if (gc == 0) {
        rs[rm][warp >> 2]     = ss0;
        rs[rm + 8][warp >> 2] = ss1;
    }
    __syncthreads();
    float r0 = rsqrtf((rs[rm][0] + rs[rm][1]) * (1.f / 64.f) + 1e-6f);
    float r1 = rsqrtf((rs[rm + 8][0] + rs[rm + 8][1]) * (1.f / 64.f) + 1e-6f);

    const int rowg = (int)row0 + rm;
    const int cbase = (hk * 4 + h) * 64;
    #pragma unroll
    for (int nt = 0; nt < 4; nt++) {
        int cl = wn + nt * 8 + gc * 2;
        int colg = cbase + cl;
        float gw0 = gnw[cl], gw1 = gnw[cl + 1];
        g_oattnH[aperm16w(rowg, colg)] =
            pack2h(acc[nt][0] * r0 * gw0, acc[nt][1] * r0 * gw1);
        g_oattnH[aperm16w(rowg + 8, colg)] =
            pack2h(acc[nt][2] * r1 * gw0, acc[nt][3] * r1 * gw1);
    }
}

// ---------------- launch -----------------------------------------------------
extern "C" void kernel_launch(void* const* d_in, const int* in_sizes, int n_in,
                              void* d_out, int out_size) {
    const float* hs  = (const float*)d_in[0];
    const float* Wq  = (const float*)d_in[1];
    const float* Wk  = (const float*)d_in[2];
    const float* Wv  = (const float*)d_in[3];
    const float* Wo  = (const float*)d_in[4];
    const float* Wg1 = (const float*)d_in[5];
    const float* Wg2 = (const float*)d_in[6];
    const float* bg2 = (const float*)d_in[7];
    const float* gnw = (const float*)d_in[8];
    float* out = (float*)d_out;

    unsigned *phstH, *poattnH, *pwqkvH, *pwoH;
    float *pqkv;
    cudaGetSymbolAddress((void**)&phstH,   g_hstH);
    cudaGetSymbolAddress((void**)&pqkv,    g_qkv);
    cudaGetSymbolAddress((void**)&poattnH, g_oattnH);
    cudaGetSymbolAddress((void**)&pwqkvH,  g_WqkvH);
    cudaGetSymbolAddress((void**)&pwoH,    g_WoH);

    cudaFuncSetAttribute(phaseC_kernel,
                         cudaFuncAttributeMaxDynamicSharedMemorySize,
                         PC_WORDS * 4);
    cudaFuncSetAttribute(mma_gemm16,
                         cudaFuncAttributeMaxDynamicSharedMemorySize,
                         HSMEM_WORDS * 4);

    // side stream + fork/join events (created once, outside graph capture)
    static cudaStream_t s1 = nullptr;
    static cudaEvent_t evFork = nullptr, evJoin = nullptr;
    if (!s1) {
        cudaStreamCreateWithFlags(&s1, cudaStreamNonBlocking);
        cudaEventCreateWithFlags(&evFork, cudaEventDisableTiming);
        cudaEventCreateWithFlags(&evJoin, cudaEventDisableTiming);
    }

    // fork: gate + Wo prep run concurrently with main chain
    cudaEventRecord(evFork, 0);
    cudaStreamWaitEvent(s1, evFork, 0);
    gate_fused<<<MROWS / 32, 256, 0, s1>>>(hs, Wg1, Wg2, bg2);
    prep_wo_h<<<1024, 256, 0, s1>>>(Wo);
    cudaEventRecord(evJoin, s1);

    // main chain: merged prep, then qkv GEMM
    prep_main<<<3584, 256>>>(Wq, Wk, Wv, hs);
    mma_gemm16<<<dim3(NQKV / 128, MROWS / 128), 256, HSMEM_WORDS * 4>>>(
        phstH, pwqkvH, pqkv, NQKV, 1280);

    // join: phaseA needs g_lg; Wo GEMM needs g_WoH
    cudaStreamWaitEvent(0, evJoin, 0);

    // chunked GLA
    phaseA_kernel<<<8 * NCHUNK, 64>>>();
    phaseB_kernel<<<64, 128>>>();
    phaseC_kernel<<<8 * 4 * NCHUNK, 256, PC_WORDS * 4>>>(gnw);

    // out = oattn @ Wo
    mma_gemm16<<<dim3(HID / 128, MROWS / 128), 256, HSMEM_WORDS * 4>>>(
        poattnH, pwoH, out, HID, 0);
}